// round 13
// baseline (speedup 1.0000x reference)
#include <cuda_runtime.h>
#include <cuda_fp16.h>
#include <math.h>

#define CD 384
#define FFD 1536
#define NQKV 1152
#define TMAX (32*64*64)

typedef __half hf;

// ---------------- scratch ----------------
__device__ hf     g_u   [(size_t)TMAX * CD];
__device__ hf     g_qkv [(size_t)TMAX * NQKV];
__device__ hf     g_obf [(size_t)TMAX * CD];
__device__ hf     g_ores[(size_t)TMAX * CD];
__device__ hf     g_u2  [(size_t)TMAX * CD];
__device__ hf     g_hbf [(size_t)TMAX * FFD];
__device__ float2 g_sc1 [TMAX];   // (mu, sig): win = u*sig + mu
__device__ float2 g_sc2 [TMAX];   // (mu, sig): x2  = u2*sig + mu
__device__ hf     g_wqkv[NQKV * CD];
__device__ float  g_bqkv[NQKV];
__device__ hf     g_opw [CD * CD];
__device__ hf     g_w1  [FFD * CD];
__device__ float  g_b1p [FFD];
__device__ hf     g_w2  [CD * FFD];

// ---------------- small helpers ----------------
__global__ void k_f2h(const float* __restrict__ s, hf* __restrict__ d, int n) {
    int i = blockIdx.x * blockDim.x + threadIdx.x;
    if (i < n) d[i] = __float2half(s[i]);
}

__global__ void k_wqkv(const float* __restrict__ ipw, const float* __restrict__ ipb,
                       const float* __restrict__ gq, const float* __restrict__ bq,
                       const float* __restrict__ gk, const float* __restrict__ bk,
                       const float* __restrict__ gv, const float* __restrict__ bv,
                       hf* __restrict__ Wo, float* __restrict__ bo) {
    __shared__ float sm[4];
    int n = blockIdx.x, tid = threadIdx.x;
    int s = n / CD;
    const float* g = (s == 0) ? gq : (s == 1) ? gk : gv;
    const float* bb = (s == 0) ? bq : (s == 1) ? bk : bv;
    float scl = (s == 0) ? 0.17677669529663687f : 1.f;
    float part = 0.f;
    for (int c = tid; c < CD; c += 128) {
        float wv = ipw[(size_t)n * CD + c];
        part += wv * bb[c];
        Wo[(size_t)n * CD + c] = __float2half(wv * g[c] * scl);
    }
    #pragma unroll
    for (int o = 16; o > 0; o >>= 1) part += __shfl_down_sync(0xffffffffu, part, o);
    if ((tid & 31) == 0) sm[tid >> 5] = part;
    __syncthreads();
    if (tid == 0) bo[n] = (ipb[n] + sm[0] + sm[1] + sm[2] + sm[3]) * scl;
}

__global__ void k_w1p(const float* __restrict__ w1, const float* __restrict__ b1,
                      const float* __restrict__ g2, const float* __restrict__ b2,
                      hf* __restrict__ Wo, float* __restrict__ bo) {
    __shared__ float sm[4];
    int n = blockIdx.x, tid = threadIdx.x;
    float part = 0.f;
    for (int c = tid; c < CD; c += 128) {
        float wv = w1[(size_t)n * CD + c];
        part += wv * b2[c];
        Wo[(size_t)n * CD + c] = __float2half(wv * g2[c]);
    }
    #pragma unroll
    for (int o = 16; o > 0; o >>= 1) part += __shfl_down_sync(0xffffffffu, part, o);
    if ((tid & 31) == 0) sm[tid >> 5] = part;
    __syncthreads();
    if (tid == 0) bo[n] = b1[n] + sm[0] + sm[1] + sm[2] + sm[3];
}

__device__ __forceinline__ int t_to_xrow(int t) {
    int w = t >> 6, l = t & 63;
    int b = w >> 6, wi = w & 63;
    int wy = wi >> 3, wx = wi & 7;
    int iy = l >> 3, ix = l & 7;
    return b * 4096 + (wy * 8 + iy) * 64 + wx * 8 + ix;
}

__device__ __forceinline__ void wreduce2(float& s0, float& s1) {
    #pragma unroll
    for (int o = 16; o > 0; o >>= 1) {
        s0 += __shfl_xor_sync(0xffffffffu, s0, o);
        s1 += __shfl_xor_sync(0xffffffffu, s1, o);
    }
}

// ---------------- LN1 + window partition: warp per token -------------------
__global__ void __launch_bounds__(256)
k_prep2(const float* __restrict__ x,
        const float* __restrict__ g1, const float* __restrict__ b1,
        hf* __restrict__ u, float2* __restrict__ sc1) {
    int wid = threadIdx.x >> 5, lane = threadIdx.x & 31;
    int t = blockIdx.x * 8 + wid;
    size_t src = (size_t)t_to_xrow(t) * CD;
    size_t dst = (size_t)t * CD;

    float4 xv[3];
    float s = 0.f, sq = 0.f;
    #pragma unroll
    for (int j = 0; j < 3; j++) {
        xv[j] = *(const float4*)(x + src + j * 128 + lane * 4);
        s += xv[j].x + xv[j].y + xv[j].z + xv[j].w;
        sq += xv[j].x * xv[j].x + xv[j].y * xv[j].y + xv[j].z * xv[j].z + xv[j].w * xv[j].w;
    }
    wreduce2(s, sq);
    float m = s * (1.f / CD);
    float r = rsqrtf(sq * (1.f / CD) - m * m + 1e-5f);

    float4 wv[3];
    s = 0.f; sq = 0.f;
    #pragma unroll
    for (int j = 0; j < 3; j++) {
        int c = j * 128 + lane * 4;
        float4 g = *(const float4*)(g1 + c);
        float4 b = *(const float4*)(b1 + c);
        wv[j].x = (xv[j].x - m) * r * g.x + b.x;
        wv[j].y = (xv[j].y - m) * r * g.y + b.y;
        wv[j].z = (xv[j].z - m) * r * g.z + b.z;
        wv[j].w = (xv[j].w - m) * r * g.w + b.w;
        s += wv[j].x + wv[j].y + wv[j].z + wv[j].w;
        sq += wv[j].x * wv[j].x + wv[j].y * wv[j].y + wv[j].z * wv[j].z + wv[j].w * wv[j].w;
    }
    wreduce2(s, sq);
    float m2 = s * (1.f / CD);
    float r2 = rsqrtf(sq * (1.f / CD) - m2 * m2 + 1e-5f);

    if (lane == 0) sc1[t] = make_float2(m2, 1.f / r2);

    #pragma unroll
    for (int j = 0; j < 3; j++) {
        int c = j * 128 + lane * 4;
        *(__half2*)(u + dst + c)     = __floats2half2_rn((wv[j].x - m2) * r2, (wv[j].y - m2) * r2);
        *(__half2*)(u + dst + c + 2) = __floats2half2_rn((wv[j].z - m2) * r2, (wv[j].w - m2) * r2);
    }
}

// ---------------- ldmatrix / mma wrappers ----------------
__device__ __forceinline__ void ldmx4(unsigned* r, const hf* p) {
    unsigned a = (unsigned)__cvta_generic_to_shared(p);
    asm volatile("ldmatrix.sync.aligned.m8n8.x4.shared.b16 {%0,%1,%2,%3}, [%4];"
                 : "=r"(r[0]), "=r"(r[1]), "=r"(r[2]), "=r"(r[3]) : "r"(a));
}
__device__ __forceinline__ void mma16816(float* c, const unsigned* a, unsigned b0, unsigned b1) {
    asm volatile(
        "mma.sync.aligned.m16n8k16.row.col.f32.f16.f16.f32 "
        "{%0,%1,%2,%3}, {%4,%5,%6,%7}, {%8,%9}, {%0,%1,%2,%3};"
        : "+f"(c[0]), "+f"(c[1]), "+f"(c[2]), "+f"(c[3])
        : "r"(a[0]), "r"(a[1]), "r"(a[2]), "r"(a[3]), "r"(b0), "r"(b1));
}
__device__ __forceinline__ void cpa16(hf* dst, const hf* src) {
    unsigned d = (unsigned)__cvta_generic_to_shared(dst);
    asm volatile("cp.async.cg.shared.global [%0], [%1], 16;" :: "r"(d), "l"(src));
}

// ------ fp16 GEMM: 128x128, K-chunk 64, 3-stage cp.async, wait_group 1 -----
// EPI: 0 = bias -> fp16, 1 = bias+GELU -> fp16,
//      4 = bias + (res*sig+mu) -> fp16,  5 = bias + (res*sig+mu) -> f32
#define SSTG 9216   // 128 rows * 72 (64 + pad 8) per matrix per stage

template <int EPI>
__global__ void __launch_bounds__(256, 2)
k_mma2(const hf* __restrict__ A, const hf* __restrict__ Wt,
       const float* __restrict__ bias, const hf* __restrict__ res,
       const float2* __restrict__ scv, void* __restrict__ outv,
       int M, int N, int K) {
    extern __shared__ hf smem[];
    hf* sA = smem;              // 3 stages
    hf* sB = smem + 3 * SSTG;   // 3 stages

    int tid  = threadIdx.x;
    int lane = tid & 31, warp = tid >> 5;
    int wm = warp >> 2, wn = warp & 3;
    int gid = lane >> 2, tg = lane & 3;
    int t8 = lane >> 3, r8 = lane & 7;
    int bn = blockIdx.x, bm = blockIdx.y;

    const hf* Ab = A  + (size_t)bm * 128 * K;
    const hf* Bb = Wt + (size_t)bn * 128 * K;

    int lrow = tid >> 1;          // 0..127
    int lc0 = (tid & 1) * 4;      // 4 x 16B chunks per thread per matrix

    float acc[4][4][4];
    #pragma unroll
    for (int i = 0; i < 4; i++)
        #pragma unroll
        for (int j = 0; j < 4; j++)
            #pragma unroll
            for (int r = 0; r < 4; r++) acc[i][j][r] = 0.f;

    int nch = K >> 6;   // 6 or 24
    // prologue: chunks 0,1 -> stages 0,1
    #pragma unroll
    for (int p = 0; p < 2; p++) {
        int k0 = p << 6;
        #pragma unroll
        for (int j = 0; j < 4; j++) {
            int c = lc0 + j;
            cpa16(sA + p * SSTG + lrow * 72 + c * 8, Ab + (size_t)lrow * K + k0 + c * 8);
            cpa16(sB + p * SSTG + lrow * 72 + c * 8, Bb + (size_t)lrow * K + k0 + c * 8);
        }
        asm volatile("cp.async.commit_group;");
    }

    for (int i = 0; i < nch; i++) {
        if (i + 1 < nch) asm volatile("cp.async.wait_group 1;");
        else             asm volatile("cp.async.wait_group 0;");
        __syncthreads();

        if (i + 2 < nch) {
            int k0 = (i + 2) << 6;
            int sp = (i + 2) % 3;
            #pragma unroll
            for (int j = 0; j < 4; j++) {
                int c = lc0 + j;
                cpa16(sA + sp * SSTG + lrow * 72 + c * 8, Ab + (size_t)lrow * K + k0 + c * 8);
                cpa16(sB + sp * SSTG + lrow * 72 + c * 8, Bb + (size_t)lrow * K + k0 + c * 8);
            }
            asm volatile("cp.async.commit_group;");
        } else {
            asm volatile("cp.async.commit_group;");
        }

        const hf* As_ = sA + (i % 3) * SSTG;
        const hf* Bs_ = sB + (i % 3) * SSTG;
        #pragma unroll
        for (int ks = 0; ks < 4; ks++) {
            int kk = ks * 16;
            unsigned af[4][4];
            #pragma unroll
            for (int mt = 0; mt < 4; mt++)
                ldmx4(af[mt], As_ + (wm * 64 + mt * 16 + (t8 & 1) * 8 + r8) * 72 + kk + (t8 >> 1) * 8);
            unsigned bfx[4][2];
            #pragma unroll
            for (int np = 0; np < 2; np++) {
                unsigned b4[4];
                ldmx4(b4, Bs_ + (wn * 32 + np * 16 + (t8 >> 1) * 8 + r8) * 72 + kk + (t8 & 1) * 8);
                bfx[np * 2][0] = b4[0]; bfx[np * 2][1] = b4[1];
                bfx[np * 2 + 1][0] = b4[2]; bfx[np * 2 + 1][1] = b4[3];
            }
            #pragma unroll
            for (int mt = 0; mt < 4; mt++)
                #pragma unroll
                for (int nt = 0; nt < 4; nt++)
                    mma16816(acc[mt][nt], af[mt], bfx[nt][0], bfx[nt][1]);
        }
    }

    float* outf = (float*)outv;
    hf*    outh = (hf*)outv;
    #pragma unroll
    for (int mt = 0; mt < 4; mt++) {
        int row0 = bm * 128 + wm * 64 + mt * 16 + gid;
        #pragma unroll
        for (int h = 0; h < 2; h++) {
            int row = row0 + h * 8;
            float mu = 0.f, sg = 0.f;
            if (EPI >= 4) { float2 sc = scv[row]; mu = sc.x; sg = sc.y; }
            #pragma unroll
            for (int nt = 0; nt < 4; nt++) {
                int col = bn * 128 + wn * 32 + nt * 8 + tg * 2;
                size_t off = (size_t)row * N + col;
                float v0 = acc[mt][nt][h * 2 + 0] + bias[col];
                float v1 = acc[mt][nt][h * 2 + 1] + bias[col + 1];
                if (EPI == 1) {
                    v0 = 0.5f * v0 * (1.f + erff(v0 * 0.70710678118654752f));
                    v1 = 0.5f * v1 * (1.f + erff(v1 * 0.70710678118654752f));
                }
                if (EPI >= 4) {
                    float2 rf = __half22float2(*(const __half2*)(res + off));
                    v0 += rf.x * sg + mu;
                    v1 += rf.y * sg + mu;
                }
                if (EPI == 5) {
                    float2 ov; ov.x = v0; ov.y = v1;
                    *(float2*)(outf + off) = ov;
                } else {
                    *(__half2*)(outh + off) = __floats2half2_rn(v0, v1);
                }
            }
        }
    }
}

// ---------------- tensor-core attention: block = (window, head) ------------
__global__ void __launch_bounds__(128)
k_attn2(const hf* __restrict__ qkv, hf* __restrict__ o) {
    __shared__ hf Qs[64 * 40];
    __shared__ hf Ks[64 * 40];
    __shared__ hf Vt[32 * 72];
    int w = blockIdx.x, hd = blockIdx.y;
    int tid = threadIdx.x, lane = tid & 31, warp = tid >> 5;
    int gid = lane >> 2, tg = lane & 3;
    int t8 = lane >> 3, r8 = lane & 7;

    const hf* base = qkv + (size_t)w * 64 * NQKV + hd * 32;
    #pragma unroll
    for (int t4 = tid; t4 < 512; t4 += 128) {
        int mtx = t4 >> 8;
        int r = (t4 >> 2) & 63;
        int c = (t4 & 3) * 8;
        uint4 v = *(const uint4*)(base + (size_t)r * NQKV + mtx * CD + c);
        *(uint4*)((mtx ? Ks : Qs) + r * 40 + c) = v;
    }
    for (int idx = tid; idx < 2048; idx += 128) {
        int l = idx >> 5, d = idx & 31;
        Vt[d * 72 + l] = base[(size_t)l * NQKV + 2 * CD + d];
    }
    __syncthreads();

    unsigned aq[2][4];
    #pragma unroll
    for (int ks = 0; ks < 2; ks++)
        ldmx4(aq[ks], Qs + (warp * 16 + (t8 & 1) * 8 + r8) * 40 + ks * 16 + (t8 >> 1) * 8);

    float acc[8][4];
    #pragma unroll
    for (int i = 0; i < 8; i++)
        #pragma unroll
        for (int j = 0; j < 4; j++) acc[i][j] = 0.f;

    #pragma unroll
    for (int ks = 0; ks < 2; ks++) {
        #pragma unroll
        for (int np = 0; np < 4; np++) {
            unsigned b4[4];
            ldmx4(b4, Ks + (np * 16 + (t8 >> 1) * 8 + r8) * 40 + ks * 16 + (t8 & 1) * 8);
            mma16816(acc[np * 2],     aq[ks], b4[0], b4[1]);
            mma16816(acc[np * 2 + 1], aq[ks], b4[2], b4[3]);
        }
    }

    float mx0 = -1e30f, mx1 = -1e30f;
    #pragma unroll
    for (int nt = 0; nt < 8; nt++) {
        mx0 = fmaxf(mx0, fmaxf(acc[nt][0], acc[nt][1]));
        mx1 = fmaxf(mx1, fmaxf(acc[nt][2], acc[nt][3]));
    }
    mx0 = fmaxf(mx0, __shfl_xor_sync(0xffffffffu, mx0, 1));
    mx0 = fmaxf(mx0, __shfl_xor_sync(0xffffffffu, mx0, 2));
    mx1 = fmaxf(mx1, __shfl_xor_sync(0xffffffffu, mx1, 1));
    mx1 = fmaxf(mx1, __shfl_xor_sync(0xffffffffu, mx1, 2));

    float s0 = 0.f, s1 = 0.f;
    #pragma unroll
    for (int nt = 0; nt < 8; nt++) {
        acc[nt][0] = __expf(acc[nt][0] - mx0); s0 += acc[nt][0];
        acc[nt][1] = __expf(acc[nt][1] - mx0); s0 += acc[nt][1];
        acc[nt][2] = __expf(acc[nt][2] - mx1); s1 += acc[nt][2];
        acc[nt][3] = __expf(acc[nt][3] - mx1); s1 += acc[nt][3];
    }
    s0 += __shfl_xor_sync(0xffffffffu, s0, 1);
    s0 += __shfl_xor_sync(0xffffffffu, s0, 2);
    s1 += __shfl_xor_sync(0xffffffffu, s1, 1);
    s1 += __shfl_xor_sync(0xffffffffu, s1, 2);
    float inv0 = 1.f / s0, inv1 = 1.f / s1;

    unsigned pa[4][4];
    #pragma unroll
    for (int j = 0; j < 4; j++) {
        __half2 p0 = __floats2half2_rn(acc[2*j][0]*inv0,   acc[2*j][1]*inv0);
        __half2 p1 = __floats2half2_rn(acc[2*j][2]*inv1,   acc[2*j][3]*inv1);
        __half2 p2 = __floats2half2_rn(acc[2*j+1][0]*inv0, acc[2*j+1][1]*inv0);
        __half2 p3 = __floats2half2_rn(acc[2*j+1][2]*inv1, acc[2*j+1][3]*inv1);
        pa[j][0] = *(unsigned*)&p0; pa[j][1] = *(unsigned*)&p1;
        pa[j][2] = *(unsigned*)&p2; pa[j][3] = *(unsigned*)&p3;
    }

    float o4[4][4];
    #pragma unroll
    for (int i = 0; i < 4; i++)
        #pragma unroll
        for (int j = 0; j < 4; j++) o4[i][j] = 0.f;

    #pragma unroll
    for (int j = 0; j < 4; j++) {
        #pragma unroll
        for (int np = 0; np < 2; np++) {
            unsigned b4[4];
            ldmx4(b4, Vt + (np * 16 + (t8 >> 1) * 8 + r8) * 72 + j * 16 + (t8 & 1) * 8);
            mma16816(o4[np * 2],     pa[j], b4[0], b4[1]);
            mma16816(o4[np * 2 + 1], pa[j], b4[2], b4[3]);
        }
    }

    int r0 = w * 64 + warp * 16 + gid;
    #pragma unroll
    for (int nt = 0; nt < 4; nt++) {
        int col = hd * 32 + nt * 8 + tg * 2;
        *(__half2*)(o + (size_t)r0 * CD + col)       = __floats2half2_rn(o4[nt][0], o4[nt][1]);
        *(__half2*)(o + (size_t)(r0 + 8) * CD + col) = __floats2half2_rn(o4[nt][2], o4[nt][3]);
    }
}

// -------- nout-LN + reverse-window + residual + LN2: warp per token --------
__global__ void __launch_bounds__(256)
k_lnout2(const hf* __restrict__ ores, const float* __restrict__ x,
         const float* __restrict__ gno, const float* __restrict__ bno,
         hf* __restrict__ u2, float2* __restrict__ sc2) {
    int wid = threadIdx.x >> 5, lane = threadIdx.x & 31;
    int t = blockIdx.x * 8 + wid;
    size_t src = (size_t)t * CD;
    int xrow = t_to_xrow(t);
    size_t dst = (size_t)xrow * CD;

    float4 ov[3];
    float s = 0.f, sq = 0.f;
    #pragma unroll
    for (int j = 0; j < 3; j++) {
        uint2 pk = *(const uint2*)(ores + src + j * 128 + lane * 4);
        float2 lo = __half22float2(*(const __half2*)&pk.x);
        float2 hi = __half22float2(*(const __half2*)&pk.y);
        ov[j].x = lo.x; ov[j].y = lo.y; ov[j].z = hi.x; ov[j].w = hi.y;
        s += ov[j].x + ov[j].y + ov[j].z + ov[j].w;
        sq += ov[j].x * ov[j].x + ov[j].y * ov[j].y + ov[j].z * ov[j].z + ov[j].w * ov[j].w;
    }
    wreduce2(s, sq);
    float m = s * (1.f / CD);
    float r = rsqrtf(sq * (1.f / CD) - m * m + 1e-5f);

    float4 xv[3];
    s = 0.f; sq = 0.f;
    #pragma unroll
    for (int j = 0; j < 3; j++) {
        int c = j * 128 + lane * 4;
        float4 g = *(const float4*)(gno + c);
        float4 b = *(const float4*)(bno + c);
        float4 xr = *(const float4*)(x + dst + c);
        xv[j].x = xr.x + (ov[j].x - m) * r * g.x + b.x;
        xv[j].y = xr.y + (ov[j].y - m) * r * g.y + b.y;
        xv[j].z = xr.z + (ov[j].z - m) * r * g.z + b.z;
        xv[j].w = xr.w + (ov[j].w - m) * r * g.w + b.w;
        s += xv[j].x + xv[j].y + xv[j].z + xv[j].w;
        sq += xv[j].x * xv[j].x + xv[j].y * xv[j].y + xv[j].z * xv[j].z + xv[j].w * xv[j].w;
    }
    wreduce2(s, sq);
    float m2 = s * (1.f / CD);
    float r2 = rsqrtf(sq * (1.f / CD) - m2 * m2 + 1e-5f);

    if (lane == 0) sc2[xrow] = make_float2(m2, 1.f / r2);

    #pragma unroll
    for (int j = 0; j < 3; j++) {
        int c = j * 128 + lane * 4;
        *(__half2*)(u2 + dst + c)     = __floats2half2_rn((xv[j].x - m2) * r2, (xv[j].y - m2) * r2);
        *(__half2*)(u2 + dst + c + 2) = __floats2half2_rn((xv[j].z - m2) * r2, (xv[j].w - m2) * r2);
    }
}

// ---------------- host launcher --------------------------------------------
extern "C" void kernel_launch(void* const* d_in, const int* in_sizes, int n_in,
                              void* d_out, int out_size) {
    const float* x   = (const float*)d_in[0];
    const float* g1  = (const float*)d_in[1];
    const float* b1  = (const float*)d_in[2];
    const float* gq  = (const float*)d_in[3];
    const float* bq  = (const float*)d_in[4];
    const float* gk  = (const float*)d_in[5];
    const float* bk  = (const float*)d_in[6];
    const float* gv  = (const float*)d_in[7];
    const float* bv  = (const float*)d_in[8];
    const float* gno = (const float*)d_in[9];
    const float* bno = (const float*)d_in[10];
    const float* ipw = (const float*)d_in[11];
    const float* ipb = (const float*)d_in[12];
    const float* opw = (const float*)d_in[13];
    const float* opb = (const float*)d_in[14];
    const float* g2n = (const float*)d_in[15];
    const float* b2n = (const float*)d_in[16];
    const float* w1  = (const float*)d_in[17];
    const float* b1f = (const float*)d_in[18];
    const float* w2  = (const float*)d_in[19];
    const float* b2f = (const float*)d_in[20];

    int B = in_sizes[0] / (64 * 64 * CD);
    int T = B * 64 * 64;
    int nW = B * 64;

    float *bqkv, *b1p;
    float2 *sc1, *sc2;
    hf *u, *qkv, *obf, *ores, *u2, *hbf, *wqkv, *opwb, *w1b, *w2b;
    cudaGetSymbolAddress((void**)&u,    g_u);
    cudaGetSymbolAddress((void**)&qkv,  g_qkv);
    cudaGetSymbolAddress((void**)&obf,  g_obf);
    cudaGetSymbolAddress((void**)&ores, g_ores);
    cudaGetSymbolAddress((void**)&u2,   g_u2);
    cudaGetSymbolAddress((void**)&hbf,  g_hbf);
    cudaGetSymbolAddress((void**)&sc1,  g_sc1);
    cudaGetSymbolAddress((void**)&sc2,  g_sc2);
    cudaGetSymbolAddress((void**)&wqkv, g_wqkv);
    cudaGetSymbolAddress((void**)&bqkv, g_bqkv);
    cudaGetSymbolAddress((void**)&opwb, g_opw);
    cudaGetSymbolAddress((void**)&w1b,  g_w1);
    cudaGetSymbolAddress((void**)&b1p,  g_b1p);
    cudaGetSymbolAddress((void**)&w2b,  g_w2);

    const int dynsmem = 3 * 2 * SSTG * (int)sizeof(hf);   // 110592
    cudaFuncSetAttribute(k_mma2<0>, cudaFuncAttributeMaxDynamicSharedMemorySize, dynsmem);
    cudaFuncSetAttribute(k_mma2<1>, cudaFuncAttributeMaxDynamicSharedMemorySize, dynsmem);
    cudaFuncSetAttribute(k_mma2<4>, cudaFuncAttributeMaxDynamicSharedMemorySize, dynsmem);
    cudaFuncSetAttribute(k_mma2<5>, cudaFuncAttributeMaxDynamicSharedMemorySize, dynsmem);

    // 0) weight prep (affines + scale folded)
    k_wqkv<<<NQKV, 128>>>(ipw, ipb, gq, bq, gk, bk, gv, bv, wqkv, bqkv);
    k_w1p<<<FFD, 128>>>(w1, b1f, g2n, b2n, w1b, b1p);
    k_f2h<<<(CD*CD  + 255) / 256, 256>>>(opw, opwb, CD*CD);
    k_f2h<<<(CD*FFD + 255) / 256, 256>>>(w2,  w2b,  CD*FFD);

    // 1) LN1 + window partition (warp per token); win folded into (u, sc1)
    k_prep2<<<T / 8, 256>>>(x, g1, b1, u, sc1);

    // 2) fused QKV projection
    dim3 thr(256);
    k_mma2<0><<<dim3(NQKV/128, T/128), thr, dynsmem>>>(u, wqkv, bqkv, nullptr, nullptr, qkv, T, NQKV, CD);

    // 3) tensor-core windowed attention
    k_attn2<<<dim3(nW, 12), 128>>>(qkv, obf);

    // 4) out_proj + residual win = u*sig+mu -> ores (fp16)
    k_mma2<4><<<dim3(CD/128, T/128), thr, dynsmem>>>(obf, opwb, opb, u, sc1, ores, T, CD, CD);

    // 5) nout-LN + reverse window + residual + LN2; x2 folded into (u2, sc2)
    k_lnout2<<<T / 8, 256>>>(ores, x, gno, bno, u2, sc2);

    // 6) MLP; final residual x2 = u2*sig+mu
    k_mma2<1><<<dim3(FFD/128, T/128), thr, dynsmem>>>(u2, w1b, b1p, nullptr, nullptr, hbf, T, FFD, CD);
    k_mma2<5><<<dim3(CD/128, T/128), thr, dynsmem>>>(hbf, w2b, b2f, u2, sc2, (float*)d_out, T, CD, FFD);
}

// round 14
// speedup vs baseline: 1.0589x; 1.0589x over previous
#include <cuda_runtime.h>
#include <cuda_fp16.h>
#include <math.h>

#define CD 384
#define FFD 1536
#define NQKV 1152
#define TMAX (32*64*64)

typedef __half hf;

// ---------------- scratch ----------------
__device__ hf     g_u   [(size_t)TMAX * CD];
__device__ hf     g_qkv [(size_t)TMAX * NQKV];
__device__ hf     g_obf [(size_t)TMAX * CD];
__device__ hf     g_ores[(size_t)TMAX * CD];
__device__ hf     g_u2  [(size_t)TMAX * CD];
__device__ hf     g_hbf [(size_t)TMAX * FFD];
__device__ float2 g_sc1 [TMAX];   // (mu, sig): win = u*sig + mu
__device__ float2 g_sc2 [TMAX];   // (mu, sig): x2  = u2*sig + mu
__device__ hf     g_wqkv[NQKV * CD];
__device__ float  g_bqkv[NQKV];
__device__ hf     g_opw [CD * CD];
__device__ hf     g_w1  [FFD * CD];
__device__ float  g_b1p [FFD];
__device__ hf     g_w2  [CD * FFD];

// ---------------- small helpers ----------------
__global__ void k_f2h(const float* __restrict__ s, hf* __restrict__ d, int n) {
    int i = blockIdx.x * blockDim.x + threadIdx.x;
    if (i < n) d[i] = __float2half(s[i]);
}

__global__ void k_wqkv(const float* __restrict__ ipw, const float* __restrict__ ipb,
                       const float* __restrict__ gq, const float* __restrict__ bq,
                       const float* __restrict__ gk, const float* __restrict__ bk,
                       const float* __restrict__ gv, const float* __restrict__ bv,
                       hf* __restrict__ Wo, float* __restrict__ bo) {
    __shared__ float sm[4];
    int n = blockIdx.x, tid = threadIdx.x;
    int s = n / CD;
    const float* g = (s == 0) ? gq : (s == 1) ? gk : gv;
    const float* bb = (s == 0) ? bq : (s == 1) ? bk : bv;
    float scl = (s == 0) ? 0.17677669529663687f : 1.f;
    float part = 0.f;
    for (int c = tid; c < CD; c += 128) {
        float wv = ipw[(size_t)n * CD + c];
        part += wv * bb[c];
        Wo[(size_t)n * CD + c] = __float2half(wv * g[c] * scl);
    }
    #pragma unroll
    for (int o = 16; o > 0; o >>= 1) part += __shfl_down_sync(0xffffffffu, part, o);
    if ((tid & 31) == 0) sm[tid >> 5] = part;
    __syncthreads();
    if (tid == 0) bo[n] = (ipb[n] + sm[0] + sm[1] + sm[2] + sm[3]) * scl;
}

__global__ void k_w1p(const float* __restrict__ w1, const float* __restrict__ b1,
                      const float* __restrict__ g2, const float* __restrict__ b2,
                      hf* __restrict__ Wo, float* __restrict__ bo) {
    __shared__ float sm[4];
    int n = blockIdx.x, tid = threadIdx.x;
    float part = 0.f;
    for (int c = tid; c < CD; c += 128) {
        float wv = w1[(size_t)n * CD + c];
        part += wv * b2[c];
        Wo[(size_t)n * CD + c] = __float2half(wv * g2[c]);
    }
    #pragma unroll
    for (int o = 16; o > 0; o >>= 1) part += __shfl_down_sync(0xffffffffu, part, o);
    if ((tid & 31) == 0) sm[tid >> 5] = part;
    __syncthreads();
    if (tid == 0) bo[n] = b1[n] + sm[0] + sm[1] + sm[2] + sm[3];
}

__device__ __forceinline__ int t_to_xrow(int t) {
    int w = t >> 6, l = t & 63;
    int b = w >> 6, wi = w & 63;
    int wy = wi >> 3, wx = wi & 7;
    int iy = l >> 3, ix = l & 7;
    return b * 4096 + (wy * 8 + iy) * 64 + wx * 8 + ix;
}

__device__ __forceinline__ void wreduce2(float& s0, float& s1) {
    #pragma unroll
    for (int o = 16; o > 0; o >>= 1) {
        s0 += __shfl_xor_sync(0xffffffffu, s0, o);
        s1 += __shfl_xor_sync(0xffffffffu, s1, o);
    }
}

// ---------------- LN1 + window partition: warp per token -------------------
__global__ void __launch_bounds__(256)
k_prep2(const float* __restrict__ x,
        const float* __restrict__ g1, const float* __restrict__ b1,
        hf* __restrict__ u, float2* __restrict__ sc1) {
    int wid = threadIdx.x >> 5, lane = threadIdx.x & 31;
    int t = blockIdx.x * 8 + wid;
    size_t src = (size_t)t_to_xrow(t) * CD;
    size_t dst = (size_t)t * CD;

    float4 xv[3];
    float s = 0.f, sq = 0.f;
    #pragma unroll
    for (int j = 0; j < 3; j++) {
        xv[j] = *(const float4*)(x + src + j * 128 + lane * 4);
        s += xv[j].x + xv[j].y + xv[j].z + xv[j].w;
        sq += xv[j].x * xv[j].x + xv[j].y * xv[j].y + xv[j].z * xv[j].z + xv[j].w * xv[j].w;
    }
    wreduce2(s, sq);
    float m = s * (1.f / CD);
    float r = rsqrtf(sq * (1.f / CD) - m * m + 1e-5f);

    float4 wv[3];
    s = 0.f; sq = 0.f;
    #pragma unroll
    for (int j = 0; j < 3; j++) {
        int c = j * 128 + lane * 4;
        float4 g = *(const float4*)(g1 + c);
        float4 b = *(const float4*)(b1 + c);
        wv[j].x = (xv[j].x - m) * r * g.x + b.x;
        wv[j].y = (xv[j].y - m) * r * g.y + b.y;
        wv[j].z = (xv[j].z - m) * r * g.z + b.z;
        wv[j].w = (xv[j].w - m) * r * g.w + b.w;
        s += wv[j].x + wv[j].y + wv[j].z + wv[j].w;
        sq += wv[j].x * wv[j].x + wv[j].y * wv[j].y + wv[j].z * wv[j].z + wv[j].w * wv[j].w;
    }
    wreduce2(s, sq);
    float m2 = s * (1.f / CD);
    float r2 = rsqrtf(sq * (1.f / CD) - m2 * m2 + 1e-5f);

    if (lane == 0) sc1[t] = make_float2(m2, 1.f / r2);

    #pragma unroll
    for (int j = 0; j < 3; j++) {
        int c = j * 128 + lane * 4;
        *(__half2*)(u + dst + c)     = __floats2half2_rn((wv[j].x - m2) * r2, (wv[j].y - m2) * r2);
        *(__half2*)(u + dst + c + 2) = __floats2half2_rn((wv[j].z - m2) * r2, (wv[j].w - m2) * r2);
    }
}

// ---------------- ldmatrix / mma wrappers ----------------
__device__ __forceinline__ void ldmx4(unsigned* r, const hf* p) {
    unsigned a = (unsigned)__cvta_generic_to_shared(p);
    asm volatile("ldmatrix.sync.aligned.m8n8.x4.shared.b16 {%0,%1,%2,%3}, [%4];"
                 : "=r"(r[0]), "=r"(r[1]), "=r"(r[2]), "=r"(r[3]) : "r"(a));
}
__device__ __forceinline__ void mma16816(float* c, const unsigned* a, unsigned b0, unsigned b1) {
    asm volatile(
        "mma.sync.aligned.m16n8k16.row.col.f32.f16.f16.f32 "
        "{%0,%1,%2,%3}, {%4,%5,%6,%7}, {%8,%9}, {%0,%1,%2,%3};"
        : "+f"(c[0]), "+f"(c[1]), "+f"(c[2]), "+f"(c[3])
        : "r"(a[0]), "r"(a[1]), "r"(a[2]), "r"(a[3]), "r"(b0), "r"(b1));
}
__device__ __forceinline__ void cpa16(hf* dst, const hf* src) {
    unsigned d = (unsigned)__cvta_generic_to_shared(dst);
    asm volatile("cp.async.cg.shared.global [%0], [%1], 16;" :: "r"(d), "l"(src));
}

// ------ fp16 GEMM: 128x128x32, 3-stage cp.async, ldmatrix (R12 best) -------
// EPI: 0 = bias -> fp16, 1 = bias+GELU -> fp16,
//      4 = bias + (res*sig+mu) -> fp16,  5 = bias + (res*sig+mu) -> f32
#define SSTG 5120   // 128*40 elems per matrix per stage

template <int EPI>
__global__ void __launch_bounds__(256, 2)
k_mma2(const hf* __restrict__ A, const hf* __restrict__ Wt,
       const float* __restrict__ bias, const hf* __restrict__ res,
       const float2* __restrict__ scv, void* __restrict__ outv,
       int M, int N, int K) {
    extern __shared__ hf smem[];
    hf* sA = smem;
    hf* sB = smem + 3 * SSTG;

    int tid  = threadIdx.x;
    int lane = tid & 31, warp = tid >> 5;
    int wm = warp >> 2, wn = warp & 3;
    int gid = lane >> 2, tg = lane & 3;
    int t8 = lane >> 3, r8 = lane & 7;
    int bn = blockIdx.x, bm = blockIdx.y;

    const hf* Ab = A  + (size_t)bm * 128 * K;
    const hf* Bb = Wt + (size_t)bn * 128 * K;

    int lrow = tid >> 1;
    int lc0 = (tid & 1) * 2;

    float acc[4][4][4];
    #pragma unroll
    for (int i = 0; i < 4; i++)
        #pragma unroll
        for (int j = 0; j < 4; j++)
            #pragma unroll
            for (int r = 0; r < 4; r++) acc[i][j][r] = 0.f;

    int nst = K >> 5;
    #pragma unroll
    for (int p = 0; p < 2; p++) {
        int k0 = p << 5;
        #pragma unroll
        for (int j = 0; j < 2; j++) {
            int c = lc0 + j;
            cpa16(sA + p * SSTG + lrow * 40 + c * 8, Ab + (size_t)lrow * K + k0 + c * 8);
            cpa16(sB + p * SSTG + lrow * 40 + c * 8, Bb + (size_t)lrow * K + k0 + c * 8);
        }
        asm volatile("cp.async.commit_group;");
    }

    for (int st = 0; st < nst; st++) {
        if (st + 1 < nst) asm volatile("cp.async.wait_group 1;");
        else              asm volatile("cp.async.wait_group 0;");
        __syncthreads();

        if (st + 2 < nst) {
            int k0 = (st + 2) << 5;
            int sp = (st + 2) % 3;
            #pragma unroll
            for (int j = 0; j < 2; j++) {
                int c = lc0 + j;
                cpa16(sA + sp * SSTG + lrow * 40 + c * 8, Ab + (size_t)lrow * K + k0 + c * 8);
                cpa16(sB + sp * SSTG + lrow * 40 + c * 8, Bb + (size_t)lrow * K + k0 + c * 8);
            }
            asm volatile("cp.async.commit_group;");
        } else {
            asm volatile("cp.async.commit_group;");
        }

        const hf* As_ = sA + (st % 3) * SSTG;
        const hf* Bs_ = sB + (st % 3) * SSTG;
        #pragma unroll
        for (int ks = 0; ks < 2; ks++) {
            int kk = ks * 16;
            unsigned af[4][4];
            #pragma unroll
            for (int mt = 0; mt < 4; mt++)
                ldmx4(af[mt], As_ + (wm * 64 + mt * 16 + (t8 & 1) * 8 + r8) * 40 + kk + (t8 >> 1) * 8);
            unsigned bfx[4][2];
            #pragma unroll
            for (int np = 0; np < 2; np++) {
                unsigned b4[4];
                ldmx4(b4, Bs_ + (wn * 32 + np * 16 + (t8 >> 1) * 8 + r8) * 40 + kk + (t8 & 1) * 8);
                bfx[np * 2][0] = b4[0]; bfx[np * 2][1] = b4[1];
                bfx[np * 2 + 1][0] = b4[2]; bfx[np * 2 + 1][1] = b4[3];
            }
            #pragma unroll
            for (int mt = 0; mt < 4; mt++)
                #pragma unroll
                for (int nt = 0; nt < 4; nt++)
                    mma16816(acc[mt][nt], af[mt], bfx[nt][0], bfx[nt][1]);
        }
    }

    float* outf = (float*)outv;
    hf*    outh = (hf*)outv;
    #pragma unroll
    for (int mt = 0; mt < 4; mt++) {
        int row0 = bm * 128 + wm * 64 + mt * 16 + gid;
        #pragma unroll
        for (int h = 0; h < 2; h++) {
            int row = row0 + h * 8;
            float mu = 0.f, sg = 0.f;
            if (EPI >= 4) { float2 sc = scv[row]; mu = sc.x; sg = sc.y; }
            #pragma unroll
            for (int nt = 0; nt < 4; nt++) {
                int col = bn * 128 + wn * 32 + nt * 8 + tg * 2;
                size_t off = (size_t)row * N + col;
                float v0 = acc[mt][nt][h * 2 + 0] + bias[col];
                float v1 = acc[mt][nt][h * 2 + 1] + bias[col + 1];
                if (EPI == 1) {
                    v0 = 0.5f * v0 * (1.f + erff(v0 * 0.70710678118654752f));
                    v1 = 0.5f * v1 * (1.f + erff(v1 * 0.70710678118654752f));
                }
                if (EPI >= 4) {
                    float2 rf = __half22float2(*(const __half2*)(res + off));
                    v0 += rf.x * sg + mu;
                    v1 += rf.y * sg + mu;
                }
                if (EPI == 5) {
                    float2 ov; ov.x = v0; ov.y = v1;
                    *(float2*)(outf + off) = ov;
                } else {
                    *(__half2*)(outh + off) = __floats2half2_rn(v0, v1);
                }
            }
        }
    }
}

// ---------------- tensor-core attention: block = (window, head) ------------
__global__ void __launch_bounds__(128)
k_attn2(const hf* __restrict__ qkv, hf* __restrict__ o) {
    __shared__ hf Qs[64 * 40];
    __shared__ hf Ks[64 * 40];
    __shared__ hf Vt[32 * 72];
    int w = blockIdx.x, hd = blockIdx.y;
    int tid = threadIdx.x, lane = tid & 31, warp = tid >> 5;
    int gid = lane >> 2, tg = lane & 3;
    int t8 = lane >> 3, r8 = lane & 7;

    const hf* base = qkv + (size_t)w * 64 * NQKV + hd * 32;
    #pragma unroll
    for (int t4 = tid; t4 < 512; t4 += 128) {
        int mtx = t4 >> 8;
        int r = (t4 >> 2) & 63;
        int c = (t4 & 3) * 8;
        uint4 v = *(const uint4*)(base + (size_t)r * NQKV + mtx * CD + c);
        *(uint4*)((mtx ? Ks : Qs) + r * 40 + c) = v;
    }
    for (int idx = tid; idx < 2048; idx += 128) {
        int l = idx >> 5, d = idx & 31;
        Vt[d * 72 + l] = base[(size_t)l * NQKV + 2 * CD + d];
    }
    __syncthreads();

    unsigned aq[2][4];
    #pragma unroll
    for (int ks = 0; ks < 2; ks++)
        ldmx4(aq[ks], Qs + (warp * 16 + (t8 & 1) * 8 + r8) * 40 + ks * 16 + (t8 >> 1) * 8);

    float acc[8][4];
    #pragma unroll
    for (int i = 0; i < 8; i++)
        #pragma unroll
        for (int j = 0; j < 4; j++) acc[i][j] = 0.f;

    #pragma unroll
    for (int ks = 0; ks < 2; ks++) {
        #pragma unroll
        for (int np = 0; np < 4; np++) {
            unsigned b4[4];
            ldmx4(b4, Ks + (np * 16 + (t8 >> 1) * 8 + r8) * 40 + ks * 16 + (t8 & 1) * 8);
            mma16816(acc[np * 2],     aq[ks], b4[0], b4[1]);
            mma16816(acc[np * 2 + 1], aq[ks], b4[2], b4[3]);
        }
    }

    float mx0 = -1e30f, mx1 = -1e30f;
    #pragma unroll
    for (int nt = 0; nt < 8; nt++) {
        mx0 = fmaxf(mx0, fmaxf(acc[nt][0], acc[nt][1]));
        mx1 = fmaxf(mx1, fmaxf(acc[nt][2], acc[nt][3]));
    }
    mx0 = fmaxf(mx0, __shfl_xor_sync(0xffffffffu, mx0, 1));
    mx0 = fmaxf(mx0, __shfl_xor_sync(0xffffffffu, mx0, 2));
    mx1 = fmaxf(mx1, __shfl_xor_sync(0xffffffffu, mx1, 1));
    mx1 = fmaxf(mx1, __shfl_xor_sync(0xffffffffu, mx1, 2));

    float s0 = 0.f, s1 = 0.f;
    #pragma unroll
    for (int nt = 0; nt < 8; nt++) {
        acc[nt][0] = __expf(acc[nt][0] - mx0); s0 += acc[nt][0];
        acc[nt][1] = __expf(acc[nt][1] - mx0); s0 += acc[nt][1];
        acc[nt][2] = __expf(acc[nt][2] - mx1); s1 += acc[nt][2];
        acc[nt][3] = __expf(acc[nt][3] - mx1); s1 += acc[nt][3];
    }
    s0 += __shfl_xor_sync(0xffffffffu, s0, 1);
    s0 += __shfl_xor_sync(0xffffffffu, s0, 2);
    s1 += __shfl_xor_sync(0xffffffffu, s1, 1);
    s1 += __shfl_xor_sync(0xffffffffu, s1, 2);
    float inv0 = 1.f / s0, inv1 = 1.f / s1;

    unsigned pa[4][4];
    #pragma unroll
    for (int j = 0; j < 4; j++) {
        __half2 p0 = __floats2half2_rn(acc[2*j][0]*inv0,   acc[2*j][1]*inv0);
        __half2 p1 = __floats2half2_rn(acc[2*j][2]*inv1,   acc[2*j][3]*inv1);
        __half2 p2 = __floats2half2_rn(acc[2*j+1][0]*inv0, acc[2*j+1][1]*inv0);
        __half2 p3 = __floats2half2_rn(acc[2*j+1][2]*inv1, acc[2*j+1][3]*inv1);
        pa[j][0] = *(unsigned*)&p0; pa[j][1] = *(unsigned*)&p1;
        pa[j][2] = *(unsigned*)&p2; pa[j][3] = *(unsigned*)&p3;
    }

    float o4[4][4];
    #pragma unroll
    for (int i = 0; i < 4; i++)
        #pragma unroll
        for (int j = 0; j < 4; j++) o4[i][j] = 0.f;

    #pragma unroll
    for (int j = 0; j < 4; j++) {
        #pragma unroll
        for (int np = 0; np < 2; np++) {
            unsigned b4[4];
            ldmx4(b4, Vt + (np * 16 + (t8 >> 1) * 8 + r8) * 72 + j * 16 + (t8 & 1) * 8);
            mma16816(o4[np * 2],     pa[j], b4[0], b4[1]);
            mma16816(o4[np * 2 + 1], pa[j], b4[2], b4[3]);
        }
    }

    int r0 = w * 64 + warp * 16 + gid;
    #pragma unroll
    for (int nt = 0; nt < 4; nt++) {
        int col = hd * 32 + nt * 8 + tg * 2;
        *(__half2*)(o + (size_t)r0 * CD + col)       = __floats2half2_rn(o4[nt][0], o4[nt][1]);
        *(__half2*)(o + (size_t)(r0 + 8) * CD + col) = __floats2half2_rn(o4[nt][2], o4[nt][3]);
    }
}

// -------- nout-LN + reverse-window + residual + LN2: warp per token --------
__global__ void __launch_bounds__(256)
k_lnout2(const hf* __restrict__ ores, const float* __restrict__ x,
         const float* __restrict__ gno, const float* __restrict__ bno,
         hf* __restrict__ u2, float2* __restrict__ sc2) {
    int wid = threadIdx.x >> 5, lane = threadIdx.x & 31;
    int t = blockIdx.x * 8 + wid;
    size_t src = (size_t)t * CD;
    int xrow = t_to_xrow(t);
    size_t dst = (size_t)xrow * CD;

    float4 ov[3];
    float s = 0.f, sq = 0.f;
    #pragma unroll
    for (int j = 0; j < 3; j++) {
        uint2 pk = *(const uint2*)(ores + src + j * 128 + lane * 4);
        float2 lo = __half22float2(*(const __half2*)&pk.x);
        float2 hi = __half22float2(*(const __half2*)&pk.y);
        ov[j].x = lo.x; ov[j].y = lo.y; ov[j].z = hi.x; ov[j].w = hi.y;
        s += ov[j].x + ov[j].y + ov[j].z + ov[j].w;
        sq += ov[j].x * ov[j].x + ov[j].y * ov[j].y + ov[j].z * ov[j].z + ov[j].w * ov[j].w;
    }
    wreduce2(s, sq);
    float m = s * (1.f / CD);
    float r = rsqrtf(sq * (1.f / CD) - m * m + 1e-5f);

    float4 xv[3];
    s = 0.f; sq = 0.f;
    #pragma unroll
    for (int j = 0; j < 3; j++) {
        int c = j * 128 + lane * 4;
        float4 g = *(const float4*)(gno + c);
        float4 b = *(const float4*)(bno + c);
        float4 xr = *(const float4*)(x + dst + c);
        xv[j].x = xr.x + (ov[j].x - m) * r * g.x + b.x;
        xv[j].y = xr.y + (ov[j].y - m) * r * g.y + b.y;
        xv[j].z = xr.z + (ov[j].z - m) * r * g.z + b.z;
        xv[j].w = xr.w + (ov[j].w - m) * r * g.w + b.w;
        s += xv[j].x + xv[j].y + xv[j].z + xv[j].w;
        sq += xv[j].x * xv[j].x + xv[j].y * xv[j].y + xv[j].z * xv[j].z + xv[j].w * xv[j].w;
    }
    wreduce2(s, sq);
    float m2 = s * (1.f / CD);
    float r2 = rsqrtf(sq * (1.f / CD) - m2 * m2 + 1e-5f);

    if (lane == 0) sc2[xrow] = make_float2(m2, 1.f / r2);

    #pragma unroll
    for (int j = 0; j < 3; j++) {
        int c = j * 128 + lane * 4;
        *(__half2*)(u2 + dst + c)     = __floats2half2_rn((xv[j].x - m2) * r2, (xv[j].y - m2) * r2);
        *(__half2*)(u2 + dst + c + 2) = __floats2half2_rn((xv[j].z - m2) * r2, (xv[j].w - m2) * r2);
    }
}

// ---------------- host launcher --------------------------------------------
extern "C" void kernel_launch(void* const* d_in, const int* in_sizes, int n_in,
                              void* d_out, int out_size) {
    const float* x   = (const float*)d_in[0];
    const float* g1  = (const float*)d_in[1];
    const float* b1  = (const float*)d_in[2];
    const float* gq  = (const float*)d_in[3];
    const float* bq  = (const float*)d_in[4];
    const float* gk  = (const float*)d_in[5];
    const float* bk  = (const float*)d_in[6];
    const float* gv  = (const float*)d_in[7];
    const float* bv  = (const float*)d_in[8];
    const float* gno = (const float*)d_in[9];
    const float* bno = (const float*)d_in[10];
    const float* ipw = (const float*)d_in[11];
    const float* ipb = (const float*)d_in[12];
    const float* opw = (const float*)d_in[13];
    const float* opb = (const float*)d_in[14];
    const float* g2n = (const float*)d_in[15];
    const float* b2n = (const float*)d_in[16];
    const float* w1  = (const float*)d_in[17];
    const float* b1f = (const float*)d_in[18];
    const float* w2  = (const float*)d_in[19];
    const float* b2f = (const float*)d_in[20];

    int B = in_sizes[0] / (64 * 64 * CD);
    int T = B * 64 * 64;
    int nW = B * 64;

    float *bqkv, *b1p;
    float2 *sc1, *sc2;
    hf *u, *qkv, *obf, *ores, *u2, *hbf, *wqkv, *opwb, *w1b, *w2b;
    cudaGetSymbolAddress((void**)&u,    g_u);
    cudaGetSymbolAddress((void**)&qkv,  g_qkv);
    cudaGetSymbolAddress((void**)&obf,  g_obf);
    cudaGetSymbolAddress((void**)&ores, g_ores);
    cudaGetSymbolAddress((void**)&u2,   g_u2);
    cudaGetSymbolAddress((void**)&hbf,  g_hbf);
    cudaGetSymbolAddress((void**)&sc1,  g_sc1);
    cudaGetSymbolAddress((void**)&sc2,  g_sc2);
    cudaGetSymbolAddress((void**)&wqkv, g_wqkv);
    cudaGetSymbolAddress((void**)&bqkv, g_bqkv);
    cudaGetSymbolAddress((void**)&opwb, g_opw);
    cudaGetSymbolAddress((void**)&w1b,  g_w1);
    cudaGetSymbolAddress((void**)&b1p,  g_b1p);
    cudaGetSymbolAddress((void**)&w2b,  g_w2);

    const int dynsmem = 3 * 2 * SSTG * (int)sizeof(hf);   // 61440
    cudaFuncSetAttribute(k_mma2<0>, cudaFuncAttributeMaxDynamicSharedMemorySize, dynsmem);
    cudaFuncSetAttribute(k_mma2<1>, cudaFuncAttributeMaxDynamicSharedMemorySize, dynsmem);
    cudaFuncSetAttribute(k_mma2<4>, cudaFuncAttributeMaxDynamicSharedMemorySize, dynsmem);
    cudaFuncSetAttribute(k_mma2<5>, cudaFuncAttributeMaxDynamicSharedMemorySize, dynsmem);

    // side stream + events for weight-prep overlap (host resources, created once)
    static cudaStream_t s2 = nullptr;
    static cudaEvent_t evFork = nullptr, evJoin = nullptr;
    if (!s2) {
        cudaStreamCreateWithFlags(&s2, cudaStreamNonBlocking);
        cudaEventCreateWithFlags(&evFork, cudaEventDisableTiming);
        cudaEventCreateWithFlags(&evJoin, cudaEventDisableTiming);
    }

    // fork: weight prep on s2, LN1 on main stream, join before QKV GEMM
    cudaEventRecord(evFork, 0);
    cudaStreamWaitEvent(s2, evFork, 0);
    k_wqkv<<<NQKV, 128, 0, s2>>>(ipw, ipb, gq, bq, gk, bk, gv, bv, wqkv, bqkv);
    k_w1p<<<FFD, 128, 0, s2>>>(w1, b1f, g2n, b2n, w1b, b1p);
    k_f2h<<<(CD*CD  + 255) / 256, 256, 0, s2>>>(opw, opwb, CD*CD);
    k_f2h<<<(CD*FFD + 255) / 256, 256, 0, s2>>>(w2,  w2b,  CD*FFD);
    cudaEventRecord(evJoin, s2);

    // 1) LN1 + window partition (warp per token) — overlaps weight prep
    k_prep2<<<T / 8, 256>>>(x, g1, b1, u, sc1);

    cudaStreamWaitEvent(0, evJoin, 0);

    // 2) fused QKV projection
    dim3 thr(256);
    k_mma2<0><<<dim3(NQKV/128, T/128), thr, dynsmem>>>(u, wqkv, bqkv, nullptr, nullptr, qkv, T, NQKV, CD);

    // 3) tensor-core windowed attention
    k_attn2<<<dim3(nW, 12), 128>>>(qkv, obf);

    // 4) out_proj + residual win = u*sig+mu -> ores (fp16)
    k_mma2<4><<<dim3(CD/128, T/128), thr, dynsmem>>>(obf, opwb, opb, u, sc1, ores, T, CD, CD);

    // 5) nout-LN + reverse window + residual + LN2; x2 folded into (u2, sc2)
    k_lnout2<<<T / 8, 256>>>(ores, x, gno, bno, u2, sc2);

    // 6) MLP; final residual x2 = u2*sig+mu
    k_mma2<1><<<dim3(FFD/128, T/128), thr, dynsmem>>>(u2, w1b, b1p, nullptr, nullptr, hbf, T, FFD, CD);
    k_mma2<5><<<dim3(CD/128, T/128), thr, dynsmem>>>(hbf, w2b, b2f, u2, sc2, (float*)d_out, T, CD, FFD);
}

// round 15
// speedup vs baseline: 1.1113x; 1.0495x over previous
#include <cuda_runtime.h>
#include <cuda_fp16.h>
#include <math.h>

#define CD 384
#define FFD 1536
#define NQKV 1152
#define TMAX (32*64*64)

typedef __half hf;

// ---------------- scratch ----------------
__device__ hf     g_u   [(size_t)TMAX * CD];
__device__ hf     g_qkv [(size_t)TMAX * NQKV];
__device__ hf     g_obf [(size_t)TMAX * CD];
__device__ hf     g_ores[(size_t)TMAX * CD];
__device__ hf     g_u2  [(size_t)TMAX * CD];
__device__ hf     g_hbf [(size_t)TMAX * FFD];
__device__ float2 g_sc1 [TMAX];   // (mu, sig): win = u*sig + mu
__device__ float2 g_sc2 [TMAX];   // (mu, sig): x2  = u2*sig + mu
__device__ hf     g_wqkv[NQKV * CD];
__device__ float  g_bqkv[NQKV];
__device__ hf     g_opw [CD * CD];
__device__ hf     g_w1  [FFD * CD];
__device__ float  g_b1p [FFD];
__device__ hf     g_w2  [CD * FFD];

// ---------------- fast GELU (tanh form, hw tanh.approx) --------------------
__device__ __forceinline__ float gelu_fast(float v) {
    float inner = 0.79788456080286536f * fmaf(0.044715f * v * v, v, v);
    float t;
    asm("tanh.approx.f32 %0, %1;" : "=f"(t) : "f"(inner));
    return 0.5f * v * (1.f + t);
}

// ---------------- small helpers ----------------
__global__ void k_f2h(const float* __restrict__ s, hf* __restrict__ d, int n) {
    int i = blockIdx.x * blockDim.x + threadIdx.x;
    if (i < n) d[i] = __float2half(s[i]);
}

__global__ void k_wqkv(const float* __restrict__ ipw, const float* __restrict__ ipb,
                       const float* __restrict__ gq, const float* __restrict__ bq,
                       const float* __restrict__ gk, const float* __restrict__ bk,
                       const float* __restrict__ gv, const float* __restrict__ bv,
                       hf* __restrict__ Wo, float* __restrict__ bo) {
    __shared__ float sm[4];
    int n = blockIdx.x, tid = threadIdx.x;
    int s = n / CD;
    const float* g = (s == 0) ? gq : (s == 1) ? gk : gv;
    const float* bb = (s == 0) ? bq : (s == 1) ? bk : bv;
    float scl = (s == 0) ? 0.17677669529663687f : 1.f;
    float part = 0.f;
    for (int c = tid; c < CD; c += 128) {
        float wv = ipw[(size_t)n * CD + c];
        part += wv * bb[c];
        Wo[(size_t)n * CD + c] = __float2half(wv * g[c] * scl);
    }
    #pragma unroll
    for (int o = 16; o > 0; o >>= 1) part += __shfl_down_sync(0xffffffffu, part, o);
    if ((tid & 31) == 0) sm[tid >> 5] = part;
    __syncthreads();
    if (tid == 0) bo[n] = (ipb[n] + sm[0] + sm[1] + sm[2] + sm[3]) * scl;
}

__global__ void k_w1p(const float* __restrict__ w1, const float* __restrict__ b1,
                      const float* __restrict__ g2, const float* __restrict__ b2,
                      hf* __restrict__ Wo, float* __restrict__ bo) {
    __shared__ float sm[4];
    int n = blockIdx.x, tid = threadIdx.x;
    float part = 0.f;
    for (int c = tid; c < CD; c += 128) {
        float wv = w1[(size_t)n * CD + c];
        part += wv * b2[c];
        Wo[(size_t)n * CD + c] = __float2half(wv * g2[c]);
    }
    #pragma unroll
    for (int o = 16; o > 0; o >>= 1) part += __shfl_down_sync(0xffffffffu, part, o);
    if ((tid & 31) == 0) sm[tid >> 5] = part;
    __syncthreads();
    if (tid == 0) bo[n] = b1[n] + sm[0] + sm[1] + sm[2] + sm[3];
}

__device__ __forceinline__ int t_to_xrow(int t) {
    int w = t >> 6, l = t & 63;
    int b = w >> 6, wi = w & 63;
    int wy = wi >> 3, wx = wi & 7;
    int iy = l >> 3, ix = l & 7;
    return b * 4096 + (wy * 8 + iy) * 64 + wx * 8 + ix;
}

__device__ __forceinline__ void wreduce2(float& s0, float& s1) {
    #pragma unroll
    for (int o = 16; o > 0; o >>= 1) {
        s0 += __shfl_xor_sync(0xffffffffu, s0, o);
        s1 += __shfl_xor_sync(0xffffffffu, s1, o);
    }
}

// ---------------- LN1 + window partition: warp per token -------------------
__global__ void __launch_bounds__(256)
k_prep2(const float* __restrict__ x,
        const float* __restrict__ g1, const float* __restrict__ b1,
        hf* __restrict__ u, float2* __restrict__ sc1) {
    int wid = threadIdx.x >> 5, lane = threadIdx.x & 31;
    int t = blockIdx.x * 8 + wid;
    size_t src = (size_t)t_to_xrow(t) * CD;
    size_t dst = (size_t)t * CD;

    float4 xv[3];
    float s = 0.f, sq = 0.f;
    #pragma unroll
    for (int j = 0; j < 3; j++) {
        xv[j] = *(const float4*)(x + src + j * 128 + lane * 4);
        s += xv[j].x + xv[j].y + xv[j].z + xv[j].w;
        sq += xv[j].x * xv[j].x + xv[j].y * xv[j].y + xv[j].z * xv[j].z + xv[j].w * xv[j].w;
    }
    wreduce2(s, sq);
    float m = s * (1.f / CD);
    float r = rsqrtf(sq * (1.f / CD) - m * m + 1e-5f);

    float4 wv[3];
    s = 0.f; sq = 0.f;
    #pragma unroll
    for (int j = 0; j < 3; j++) {
        int c = j * 128 + lane * 4;
        float4 g = *(const float4*)(g1 + c);
        float4 b = *(const float4*)(b1 + c);
        wv[j].x = (xv[j].x - m) * r * g.x + b.x;
        wv[j].y = (xv[j].y - m) * r * g.y + b.y;
        wv[j].z = (xv[j].z - m) * r * g.z + b.z;
        wv[j].w = (xv[j].w - m) * r * g.w + b.w;
        s += wv[j].x + wv[j].y + wv[j].z + wv[j].w;
        sq += wv[j].x * wv[j].x + wv[j].y * wv[j].y + wv[j].z * wv[j].z + wv[j].w * wv[j].w;
    }
    wreduce2(s, sq);
    float m2 = s * (1.f / CD);
    float r2 = rsqrtf(sq * (1.f / CD) - m2 * m2 + 1e-5f);

    if (lane == 0) sc1[t] = make_float2(m2, 1.f / r2);

    #pragma unroll
    for (int j = 0; j < 3; j++) {
        int c = j * 128 + lane * 4;
        *(__half2*)(u + dst + c)     = __floats2half2_rn((wv[j].x - m2) * r2, (wv[j].y - m2) * r2);
        *(__half2*)(u + dst + c + 2) = __floats2half2_rn((wv[j].z - m2) * r2, (wv[j].w - m2) * r2);
    }
}

// ---------------- ldmatrix / mma wrappers ----------------
__device__ __forceinline__ void ldmx4(unsigned* r, const hf* p) {
    unsigned a = (unsigned)__cvta_generic_to_shared(p);
    asm volatile("ldmatrix.sync.aligned.m8n8.x4.shared.b16 {%0,%1,%2,%3}, [%4];"
                 : "=r"(r[0]), "=r"(r[1]), "=r"(r[2]), "=r"(r[3]) : "r"(a));
}
__device__ __forceinline__ void mma16816(float* c, const unsigned* a, unsigned b0, unsigned b1) {
    asm volatile(
        "mma.sync.aligned.m16n8k16.row.col.f32.f16.f16.f32 "
        "{%0,%1,%2,%3}, {%4,%5,%6,%7}, {%8,%9}, {%0,%1,%2,%3};"
        : "+f"(c[0]), "+f"(c[1]), "+f"(c[2]), "+f"(c[3])
        : "r"(a[0]), "r"(a[1]), "r"(a[2]), "r"(a[3]), "r"(b0), "r"(b1));
}
__device__ __forceinline__ void cpa16(hf* dst, const hf* src) {
    unsigned d = (unsigned)__cvta_generic_to_shared(dst);
    asm volatile("cp.async.cg.shared.global [%0], [%1], 16;" :: "r"(d), "l"(src));
}

// ------ fp16 GEMM: 128x128x32, 3-stage cp.async, ldmatrix ------------------
// EPI: 0 = bias -> fp16, 1 = bias+GELU(fast) -> fp16,
//      4 = bias + (res*sig+mu) -> fp16,  5 = bias + (res*sig+mu) -> f32
#define SSTG 5120   // 128*40 elems per matrix per stage

template <int EPI>
__global__ void __launch_bounds__(256, 2)
k_mma2(const hf* __restrict__ A, const hf* __restrict__ Wt,
       const float* __restrict__ bias, const hf* __restrict__ res,
       const float2* __restrict__ scv, void* __restrict__ outv,
       int M, int N, int K) {
    extern __shared__ hf smem[];
    hf* sA = smem;
    hf* sB = smem + 3 * SSTG;

    int tid  = threadIdx.x;
    int lane = tid & 31, warp = tid >> 5;
    int wm = warp >> 2, wn = warp & 3;
    int gid = lane >> 2, tg = lane & 3;
    int t8 = lane >> 3, r8 = lane & 7;
    int bn = blockIdx.x, bm = blockIdx.y;

    const hf* Ab = A  + (size_t)bm * 128 * K;
    const hf* Bb = Wt + (size_t)bn * 128 * K;

    int lrow = tid >> 1;
    int lc0 = (tid & 1) * 2;

    float acc[4][4][4];
    #pragma unroll
    for (int i = 0; i < 4; i++)
        #pragma unroll
        for (int j = 0; j < 4; j++)
            #pragma unroll
            for (int r = 0; r < 4; r++) acc[i][j][r] = 0.f;

    int nst = K >> 5;
    #pragma unroll
    for (int p = 0; p < 2; p++) {
        int k0 = p << 5;
        #pragma unroll
        for (int j = 0; j < 2; j++) {
            int c = lc0 + j;
            cpa16(sA + p * SSTG + lrow * 40 + c * 8, Ab + (size_t)lrow * K + k0 + c * 8);
            cpa16(sB + p * SSTG + lrow * 40 + c * 8, Bb + (size_t)lrow * K + k0 + c * 8);
        }
        asm volatile("cp.async.commit_group;");
    }

    for (int st = 0; st < nst; st++) {
        if (st + 1 < nst) asm volatile("cp.async.wait_group 1;");
        else              asm volatile("cp.async.wait_group 0;");
        __syncthreads();

        if (st + 2 < nst) {
            int k0 = (st + 2) << 5;
            int sp = (st + 2) % 3;
            #pragma unroll
            for (int j = 0; j < 2; j++) {
                int c = lc0 + j;
                cpa16(sA + sp * SSTG + lrow * 40 + c * 8, Ab + (size_t)lrow * K + k0 + c * 8);
                cpa16(sB + sp * SSTG + lrow * 40 + c * 8, Bb + (size_t)lrow * K + k0 + c * 8);
            }
            asm volatile("cp.async.commit_group;");
        } else {
            asm volatile("cp.async.commit_group;");
        }

        const hf* As_ = sA + (st % 3) * SSTG;
        const hf* Bs_ = sB + (st % 3) * SSTG;
        #pragma unroll
        for (int ks = 0; ks < 2; ks++) {
            int kk = ks * 16;
            unsigned af[4][4];
            #pragma unroll
            for (int mt = 0; mt < 4; mt++)
                ldmx4(af[mt], As_ + (wm * 64 + mt * 16 + (t8 & 1) * 8 + r8) * 40 + kk + (t8 >> 1) * 8);
            unsigned bfx[4][2];
            #pragma unroll
            for (int np = 0; np < 2; np++) {
                unsigned b4[4];
                ldmx4(b4, Bs_ + (wn * 32 + np * 16 + (t8 >> 1) * 8 + r8) * 40 + kk + (t8 & 1) * 8);
                bfx[np * 2][0] = b4[0]; bfx[np * 2][1] = b4[1];
                bfx[np * 2 + 1][0] = b4[2]; bfx[np * 2 + 1][1] = b4[3];
            }
            #pragma unroll
            for (int mt = 0; mt < 4; mt++)
                #pragma unroll
                for (int nt = 0; nt < 4; nt++)
                    mma16816(acc[mt][nt], af[mt], bfx[nt][0], bfx[nt][1]);
        }
    }

    float* outf = (float*)outv;
    hf*    outh = (hf*)outv;
    #pragma unroll
    for (int mt = 0; mt < 4; mt++) {
        int row0 = bm * 128 + wm * 64 + mt * 16 + gid;
        #pragma unroll
        for (int h = 0; h < 2; h++) {
            int row = row0 + h * 8;
            float mu = 0.f, sg = 0.f;
            if (EPI >= 4) { float2 sc = scv[row]; mu = sc.x; sg = sc.y; }
            #pragma unroll
            for (int nt = 0; nt < 4; nt++) {
                int col = bn * 128 + wn * 32 + nt * 8 + tg * 2;
                size_t off = (size_t)row * N + col;
                float v0 = acc[mt][nt][h * 2 + 0] + bias[col];
                float v1 = acc[mt][nt][h * 2 + 1] + bias[col + 1];
                if (EPI == 1) {
                    v0 = gelu_fast(v0);
                    v1 = gelu_fast(v1);
                }
                if (EPI >= 4) {
                    float2 rf = __half22float2(*(const __half2*)(res + off));
                    v0 += rf.x * sg + mu;
                    v1 += rf.y * sg + mu;
                }
                if (EPI == 5) {
                    float2 ov; ov.x = v0; ov.y = v1;
                    *(float2*)(outf + off) = ov;
                } else {
                    *(__half2*)(outh + off) = __floats2half2_rn(v0, v1);
                }
            }
        }
    }
}

// ---------------- tensor-core attention: block = (window, head) ------------
__global__ void __launch_bounds__(128)
k_attn2(const hf* __restrict__ qkv, hf* __restrict__ o) {
    __shared__ hf Qs[64 * 40];
    __shared__ hf Ks[64 * 40];
    __shared__ hf Vt[32 * 72];
    int w = blockIdx.x, hd = blockIdx.y;
    int tid = threadIdx.x, lane = tid & 31, warp = tid >> 5;
    int gid = lane >> 2, tg = lane & 3;
    int t8 = lane >> 3, r8 = lane & 7;

    const hf* base = qkv + (size_t)w * 64 * NQKV + hd * 32;
    #pragma unroll
    for (int t4 = tid; t4 < 512; t4 += 128) {
        int mtx = t4 >> 8;
        int r = (t4 >> 2) & 63;
        int c = (t4 & 3) * 8;
        uint4 v = *(const uint4*)(base + (size_t)r * NQKV + mtx * CD + c);
        *(uint4*)((mtx ? Ks : Qs) + r * 40 + c) = v;
    }
    for (int idx = tid; idx < 2048; idx += 128) {
        int l = idx >> 5, d = idx & 31;
        Vt[d * 72 + l] = base[(size_t)l * NQKV + 2 * CD + d];
    }
    __syncthreads();

    unsigned aq[2][4];
    #pragma unroll
    for (int ks = 0; ks < 2; ks++)
        ldmx4(aq[ks], Qs + (warp * 16 + (t8 & 1) * 8 + r8) * 40 + ks * 16 + (t8 >> 1) * 8);

    float acc[8][4];
    #pragma unroll
    for (int i = 0; i < 8; i++)
        #pragma unroll
        for (int j = 0; j < 4; j++) acc[i][j] = 0.f;

    #pragma unroll
    for (int ks = 0; ks < 2; ks++) {
        #pragma unroll
        for (int np = 0; np < 4; np++) {
            unsigned b4[4];
            ldmx4(b4, Ks + (np * 16 + (t8 >> 1) * 8 + r8) * 40 + ks * 16 + (t8 & 1) * 8);
            mma16816(acc[np * 2],     aq[ks], b4[0], b4[1]);
            mma16816(acc[np * 2 + 1], aq[ks], b4[2], b4[3]);
        }
    }

    float mx0 = -1e30f, mx1 = -1e30f;
    #pragma unroll
    for (int nt = 0; nt < 8; nt++) {
        mx0 = fmaxf(mx0, fmaxf(acc[nt][0], acc[nt][1]));
        mx1 = fmaxf(mx1, fmaxf(acc[nt][2], acc[nt][3]));
    }
    mx0 = fmaxf(mx0, __shfl_xor_sync(0xffffffffu, mx0, 1));
    mx0 = fmaxf(mx0, __shfl_xor_sync(0xffffffffu, mx0, 2));
    mx1 = fmaxf(mx1, __shfl_xor_sync(0xffffffffu, mx1, 1));
    mx1 = fmaxf(mx1, __shfl_xor_sync(0xffffffffu, mx1, 2));

    float s0 = 0.f, s1 = 0.f;
    #pragma unroll
    for (int nt = 0; nt < 8; nt++) {
        acc[nt][0] = __expf(acc[nt][0] - mx0); s0 += acc[nt][0];
        acc[nt][1] = __expf(acc[nt][1] - mx0); s0 += acc[nt][1];
        acc[nt][2] = __expf(acc[nt][2] - mx1); s1 += acc[nt][2];
        acc[nt][3] = __expf(acc[nt][3] - mx1); s1 += acc[nt][3];
    }
    s0 += __shfl_xor_sync(0xffffffffu, s0, 1);
    s0 += __shfl_xor_sync(0xffffffffu, s0, 2);
    s1 += __shfl_xor_sync(0xffffffffu, s1, 1);
    s1 += __shfl_xor_sync(0xffffffffu, s1, 2);
    float inv0 = 1.f / s0, inv1 = 1.f / s1;

    unsigned pa[4][4];
    #pragma unroll
    for (int j = 0; j < 4; j++) {
        __half2 p0 = __floats2half2_rn(acc[2*j][0]*inv0,   acc[2*j][1]*inv0);
        __half2 p1 = __floats2half2_rn(acc[2*j][2]*inv1,   acc[2*j][3]*inv1);
        __half2 p2 = __floats2half2_rn(acc[2*j+1][0]*inv0, acc[2*j+1][1]*inv0);
        __half2 p3 = __floats2half2_rn(acc[2*j+1][2]*inv1, acc[2*j+1][3]*inv1);
        pa[j][0] = *(unsigned*)&p0; pa[j][1] = *(unsigned*)&p1;
        pa[j][2] = *(unsigned*)&p2; pa[j][3] = *(unsigned*)&p3;
    }

    float o4[4][4];
    #pragma unroll
    for (int i = 0; i < 4; i++)
        #pragma unroll
        for (int j = 0; j < 4; j++) o4[i][j] = 0.f;

    #pragma unroll
    for (int j = 0; j < 4; j++) {
        #pragma unroll
        for (int np = 0; np < 2; np++) {
            unsigned b4[4];
            ldmx4(b4, Vt + (np * 16 + (t8 >> 1) * 8 + r8) * 72 + j * 16 + (t8 & 1) * 8);
            mma16816(o4[np * 2],     pa[j], b4[0], b4[1]);
            mma16816(o4[np * 2 + 1], pa[j], b4[2], b4[3]);
        }
    }

    int r0 = w * 64 + warp * 16 + gid;
    #pragma unroll
    for (int nt = 0; nt < 4; nt++) {
        int col = hd * 32 + nt * 8 + tg * 2;
        *(__half2*)(o + (size_t)r0 * CD + col)       = __floats2half2_rn(o4[nt][0], o4[nt][1]);
        *(__half2*)(o + (size_t)(r0 + 8) * CD + col) = __floats2half2_rn(o4[nt][2], o4[nt][3]);
    }
}

// -------- nout-LN + reverse-window + residual + LN2: warp per token --------
__global__ void __launch_bounds__(256)
k_lnout2(const hf* __restrict__ ores, const float* __restrict__ x,
         const float* __restrict__ gno, const float* __restrict__ bno,
         hf* __restrict__ u2, float2* __restrict__ sc2) {
    int wid = threadIdx.x >> 5, lane = threadIdx.x & 31;
    int t = blockIdx.x * 8 + wid;
    size_t src = (size_t)t * CD;
    int xrow = t_to_xrow(t);
    size_t dst = (size_t)xrow * CD;

    float4 ov[3];
    float s = 0.f, sq = 0.f;
    #pragma unroll
    for (int j = 0; j < 3; j++) {
        uint2 pk = *(const uint2*)(ores + src + j * 128 + lane * 4);
        float2 lo = __half22float2(*(const __half2*)&pk.x);
        float2 hi = __half22float2(*(const __half2*)&pk.y);
        ov[j].x = lo.x; ov[j].y = lo.y; ov[j].z = hi.x; ov[j].w = hi.y;
        s += ov[j].x + ov[j].y + ov[j].z + ov[j].w;
        sq += ov[j].x * ov[j].x + ov[j].y * ov[j].y + ov[j].z * ov[j].z + ov[j].w * ov[j].w;
    }
    wreduce2(s, sq);
    float m = s * (1.f / CD);
    float r = rsqrtf(sq * (1.f / CD) - m * m + 1e-5f);

    float4 xv[3];
    s = 0.f; sq = 0.f;
    #pragma unroll
    for (int j = 0; j < 3; j++) {
        int c = j * 128 + lane * 4;
        float4 g = *(const float4*)(gno + c);
        float4 b = *(const float4*)(bno + c);
        float4 xr = *(const float4*)(x + dst + c);
        xv[j].x = xr.x + (ov[j].x - m) * r * g.x + b.x;
        xv[j].y = xr.y + (ov[j].y - m) * r * g.y + b.y;
        xv[j].z = xr.z + (ov[j].z - m) * r * g.z + b.z;
        xv[j].w = xr.w + (ov[j].w - m) * r * g.w + b.w;
        s += xv[j].x + xv[j].y + xv[j].z + xv[j].w;
        sq += xv[j].x * xv[j].x + xv[j].y * xv[j].y + xv[j].z * xv[j].z + xv[j].w * xv[j].w;
    }
    wreduce2(s, sq);
    float m2 = s * (1.f / CD);
    float r2 = rsqrtf(sq * (1.f / CD) - m2 * m2 + 1e-5f);

    if (lane == 0) sc2[xrow] = make_float2(m2, 1.f / r2);

    #pragma unroll
    for (int j = 0; j < 3; j++) {
        int c = j * 128 + lane * 4;
        *(__half2*)(u2 + dst + c)     = __floats2half2_rn((xv[j].x - m2) * r2, (xv[j].y - m2) * r2);
        *(__half2*)(u2 + dst + c + 2) = __floats2half2_rn((xv[j].z - m2) * r2, (xv[j].w - m2) * r2);
    }
}

// ---------------- host launcher --------------------------------------------
extern "C" void kernel_launch(void* const* d_in, const int* in_sizes, int n_in,
                              void* d_out, int out_size) {
    const float* x   = (const float*)d_in[0];
    const float* g1  = (const float*)d_in[1];
    const float* b1  = (const float*)d_in[2];
    const float* gq  = (const float*)d_in[3];
    const float* bq  = (const float*)d_in[4];
    const float* gk  = (const float*)d_in[5];
    const float* bk  = (const float*)d_in[6];
    const float* gv  = (const float*)d_in[7];
    const float* bv  = (const float*)d_in[8];
    const float* gno = (const float*)d_in[9];
    const float* bno = (const float*)d_in[10];
    const float* ipw = (const float*)d_in[11];
    const float* ipb = (const float*)d_in[12];
    const float* opw = (const float*)d_in[13];
    const float* opb = (const float*)d_in[14];
    const float* g2n = (const float*)d_in[15];
    const float* b2n = (const float*)d_in[16];
    const float* w1  = (const float*)d_in[17];
    const float* b1f = (const float*)d_in[18];
    const float* w2  = (const float*)d_in[19];
    const float* b2f = (const float*)d_in[20];

    int B = in_sizes[0] / (64 * 64 * CD);
    int T = B * 64 * 64;
    int nW = B * 64;

    float *bqkv, *b1p;
    float2 *sc1, *sc2;
    hf *u, *qkv, *obf, *ores, *u2, *hbf, *wqkv, *opwb, *w1b, *w2b;
    cudaGetSymbolAddress((void**)&u,    g_u);
    cudaGetSymbolAddress((void**)&qkv,  g_qkv);
    cudaGetSymbolAddress((void**)&obf,  g_obf);
    cudaGetSymbolAddress((void**)&ores, g_ores);
    cudaGetSymbolAddress((void**)&u2,   g_u2);
    cudaGetSymbolAddress((void**)&hbf,  g_hbf);
    cudaGetSymbolAddress((void**)&sc1,  g_sc1);
    cudaGetSymbolAddress((void**)&sc2,  g_sc2);
    cudaGetSymbolAddress((void**)&wqkv, g_wqkv);
    cudaGetSymbolAddress((void**)&bqkv, g_bqkv);
    cudaGetSymbolAddress((void**)&opwb, g_opw);
    cudaGetSymbolAddress((void**)&w1b,  g_w1);
    cudaGetSymbolAddress((void**)&b1p,  g_b1p);
    cudaGetSymbolAddress((void**)&w2b,  g_w2);

    const int dynsmem = 3 * 2 * SSTG * (int)sizeof(hf);   // 61440
    cudaFuncSetAttribute(k_mma2<0>, cudaFuncAttributeMaxDynamicSharedMemorySize, dynsmem);
    cudaFuncSetAttribute(k_mma2<1>, cudaFuncAttributeMaxDynamicSharedMemorySize, dynsmem);
    cudaFuncSetAttribute(k_mma2<4>, cudaFuncAttributeMaxDynamicSharedMemorySize, dynsmem);
    cudaFuncSetAttribute(k_mma2<5>, cudaFuncAttributeMaxDynamicSharedMemorySize, dynsmem);

    // side stream + events for weight-prep overlap
    static cudaStream_t s2 = nullptr;
    static cudaEvent_t evFork = nullptr, evJoin = nullptr;
    if (!s2) {
        cudaStreamCreateWithFlags(&s2, cudaStreamNonBlocking);
        cudaEventCreateWithFlags(&evFork, cudaEventDisableTiming);
        cudaEventCreateWithFlags(&evJoin, cudaEventDisableTiming);
    }

    cudaEventRecord(evFork, 0);
    cudaStreamWaitEvent(s2, evFork, 0);
    k_wqkv<<<NQKV, 128, 0, s2>>>(ipw, ipb, gq, bq, gk, bk, gv, bv, wqkv, bqkv);
    k_w1p<<<FFD, 128, 0, s2>>>(w1, b1f, g2n, b2n, w1b, b1p);
    k_f2h<<<(CD*CD  + 255) / 256, 256, 0, s2>>>(opw, opwb, CD*CD);
    k_f2h<<<(CD*FFD + 255) / 256, 256, 0, s2>>>(w2,  w2b,  CD*FFD);
    cudaEventRecord(evJoin, s2);

    // 1) LN1 + window partition — overlaps weight prep
    k_prep2<<<T / 8, 256>>>(x, g1, b1, u, sc1);

    cudaStreamWaitEvent(0, evJoin, 0);

    // 2) fused QKV projection
    dim3 thr(256);
    k_mma2<0><<<dim3(NQKV/128, T/128), thr, dynsmem>>>(u, wqkv, bqkv, nullptr, nullptr, qkv, T, NQKV, CD);

    // 3) tensor-core windowed attention
    k_attn2<<<dim3(nW, 12), 128>>>(qkv, obf);

    // 4) out_proj + residual win = u*sig+mu -> ores (fp16)
    k_mma2<4><<<dim3(CD/128, T/128), thr, dynsmem>>>(obf, opwb, opb, u, sc1, ores, T, CD, CD);

    // 5) nout-LN + reverse window + residual + LN2
    k_lnout2<<<T / 8, 256>>>(ores, x, gno, bno, u2, sc2);

    // 6) MLP (fast-tanh GELU in epilogue)
    k_mma2<1><<<dim3(FFD/128, T/128), thr, dynsmem>>>(u2, w1b, b1p, nullptr, nullptr, hbf, T, FFD, CD);
    k_mma2<5><<<dim3(CD/128, T/128), thr, dynsmem>>>(hbf, w2b, b2f, u2, sc2, (float*)d_out, T, CD, FFD);
}

// round 16
// speedup vs baseline: 1.1470x; 1.0321x over previous
#include <cuda_runtime.h>
#include <cuda_fp16.h>
#include <math.h>

#define CD 384
#define FFD 1536
#define NQKV 1152
#define TMAX (32*64*64)

typedef __half hf;

// ---------------- scratch ----------------
__device__ hf     g_u   [(size_t)TMAX * CD];
__device__ hf     g_qkv [(size_t)TMAX * NQKV];
__device__ hf     g_obf [(size_t)TMAX * CD];
__device__ hf     g_ores[(size_t)TMAX * CD];
__device__ hf     g_u2  [(size_t)TMAX * CD];
__device__ hf     g_hbf [(size_t)TMAX * FFD];
__device__ float2 g_sc1 [TMAX];   // (mu, sig): win = u*sig + mu
__device__ float2 g_sc2 [TMAX];   // (mu, sig): x2  = u2*sig + mu
__device__ hf     g_wqkv[NQKV * CD];
__device__ float  g_bqkv[NQKV];
__device__ hf     g_opw [CD * CD];
__device__ hf     g_w1  [FFD * CD];
__device__ float  g_b1p [FFD];
__device__ hf     g_w2  [CD * FFD];

// ---------------- fast math helpers ----------------
__device__ __forceinline__ float gelu_fast(float v) {
    float inner = 0.79788456080286536f * fmaf(0.044715f * v * v, v, v);
    float t;
    asm("tanh.approx.f32 %0, %1;" : "=f"(t) : "f"(inner));
    return 0.5f * v * (1.f + t);
}
__device__ __forceinline__ float ex2f(float v) {
    float r;
    asm("ex2.approx.f32 %0, %1;" : "=f"(r) : "f"(v));
    return r;
}
__device__ __forceinline__ float rcpf(float v) {
    float r;
    asm("rcp.approx.f32 %0, %1;" : "=f"(r) : "f"(v));
    return r;
}

// ---------------- small helpers ----------------
__global__ void k_f2h(const float* __restrict__ s, hf* __restrict__ d, int n) {
    int i = blockIdx.x * blockDim.x + threadIdx.x;
    if (i < n) d[i] = __float2half(s[i]);
}

__global__ void k_wqkv(const float* __restrict__ ipw, const float* __restrict__ ipb,
                       const float* __restrict__ gq, const float* __restrict__ bq,
                       const float* __restrict__ gk, const float* __restrict__ bk,
                       const float* __restrict__ gv, const float* __restrict__ bv,
                       hf* __restrict__ Wo, float* __restrict__ bo) {
    __shared__ float sm[4];
    int n = blockIdx.x, tid = threadIdx.x;
    int s = n / CD;
    const float* g = (s == 0) ? gq : (s == 1) ? gk : gv;
    const float* bb = (s == 0) ? bq : (s == 1) ? bk : bv;
    // Q scale: 1/sqrt(32) * log2(e)  (softmax runs in exp2 domain)
    float scl = (s == 0) ? 0.25506977234862308f : 1.f;
    float part = 0.f;
    for (int c = tid; c < CD; c += 128) {
        float wv = ipw[(size_t)n * CD + c];
        part += wv * bb[c];
        Wo[(size_t)n * CD + c] = __float2half(wv * g[c] * scl);
    }
    #pragma unroll
    for (int o = 16; o > 0; o >>= 1) part += __shfl_down_sync(0xffffffffu, part, o);
    if ((tid & 31) == 0) sm[tid >> 5] = part;
    __syncthreads();
    if (tid == 0) bo[n] = (ipb[n] + sm[0] + sm[1] + sm[2] + sm[3]) * scl;
}

__global__ void k_w1p(const float* __restrict__ w1, const float* __restrict__ b1,
                      const float* __restrict__ g2, const float* __restrict__ b2,
                      hf* __restrict__ Wo, float* __restrict__ bo) {
    __shared__ float sm[4];
    int n = blockIdx.x, tid = threadIdx.x;
    float part = 0.f;
    for (int c = tid; c < CD; c += 128) {
        float wv = w1[(size_t)n * CD + c];
        part += wv * b2[c];
        Wo[(size_t)n * CD + c] = __float2half(wv * g2[c]);
    }
    #pragma unroll
    for (int o = 16; o > 0; o >>= 1) part += __shfl_down_sync(0xffffffffu, part, o);
    if ((tid & 31) == 0) sm[tid >> 5] = part;
    __syncthreads();
    if (tid == 0) bo[n] = b1[n] + sm[0] + sm[1] + sm[2] + sm[3];
}

__device__ __forceinline__ int t_to_xrow(int t) {
    int w = t >> 6, l = t & 63;
    int b = w >> 6, wi = w & 63;
    int wy = wi >> 3, wx = wi & 7;
    int iy = l >> 3, ix = l & 7;
    return b * 4096 + (wy * 8 + iy) * 64 + wx * 8 + ix;
}

__device__ __forceinline__ void wreduce2(float& s0, float& s1) {
    #pragma unroll
    for (int o = 16; o > 0; o >>= 1) {
        s0 += __shfl_xor_sync(0xffffffffu, s0, o);
        s1 += __shfl_xor_sync(0xffffffffu, s1, o);
    }
}

// ---------------- LN1 + window partition: warp per token -------------------
__global__ void __launch_bounds__(256)
k_prep2(const float* __restrict__ x,
        const float* __restrict__ g1, const float* __restrict__ b1,
        hf* __restrict__ u, float2* __restrict__ sc1) {
    int wid = threadIdx.x >> 5, lane = threadIdx.x & 31;
    int t = blockIdx.x * 8 + wid;
    size_t src = (size_t)t_to_xrow(t) * CD;
    size_t dst = (size_t)t * CD;

    float4 xv[3];
    float s = 0.f, sq = 0.f;
    #pragma unroll
    for (int j = 0; j < 3; j++) {
        xv[j] = *(const float4*)(x + src + j * 128 + lane * 4);
        s += xv[j].x + xv[j].y + xv[j].z + xv[j].w;
        sq += xv[j].x * xv[j].x + xv[j].y * xv[j].y + xv[j].z * xv[j].z + xv[j].w * xv[j].w;
    }
    wreduce2(s, sq);
    float m = s * (1.f / CD);
    float r = rsqrtf(sq * (1.f / CD) - m * m + 1e-5f);

    float4 wv[3];
    s = 0.f; sq = 0.f;
    #pragma unroll
    for (int j = 0; j < 3; j++) {
        int c = j * 128 + lane * 4;
        float4 g = *(const float4*)(g1 + c);
        float4 b = *(const float4*)(b1 + c);
        wv[j].x = (xv[j].x - m) * r * g.x + b.x;
        wv[j].y = (xv[j].y - m) * r * g.y + b.y;
        wv[j].z = (xv[j].z - m) * r * g.z + b.z;
        wv[j].w = (xv[j].w - m) * r * g.w + b.w;
        s += wv[j].x + wv[j].y + wv[j].z + wv[j].w;
        sq += wv[j].x * wv[j].x + wv[j].y * wv[j].y + wv[j].z * wv[j].z + wv[j].w * wv[j].w;
    }
    wreduce2(s, sq);
    float m2 = s * (1.f / CD);
    float r2 = rsqrtf(sq * (1.f / CD) - m2 * m2 + 1e-5f);

    if (lane == 0) sc1[t] = make_float2(m2, 1.f / r2);

    #pragma unroll
    for (int j = 0; j < 3; j++) {
        int c = j * 128 + lane * 4;
        *(__half2*)(u + dst + c)     = __floats2half2_rn((wv[j].x - m2) * r2, (wv[j].y - m2) * r2);
        *(__half2*)(u + dst + c + 2) = __floats2half2_rn((wv[j].z - m2) * r2, (wv[j].w - m2) * r2);
    }
}

// ---------------- ldmatrix / mma wrappers ----------------
__device__ __forceinline__ void ldmx4(unsigned* r, const hf* p) {
    unsigned a = (unsigned)__cvta_generic_to_shared(p);
    asm volatile("ldmatrix.sync.aligned.m8n8.x4.shared.b16 {%0,%1,%2,%3}, [%4];"
                 : "=r"(r[0]), "=r"(r[1]), "=r"(r[2]), "=r"(r[3]) : "r"(a));
}
__device__ __forceinline__ void mma16816(float* c, const unsigned* a, unsigned b0, unsigned b1) {
    asm volatile(
        "mma.sync.aligned.m16n8k16.row.col.f32.f16.f16.f32 "
        "{%0,%1,%2,%3}, {%4,%5,%6,%7}, {%8,%9}, {%0,%1,%2,%3};"
        : "+f"(c[0]), "+f"(c[1]), "+f"(c[2]), "+f"(c[3])
        : "r"(a[0]), "r"(a[1]), "r"(a[2]), "r"(a[3]), "r"(b0), "r"(b1));
}
__device__ __forceinline__ void cpa16(hf* dst, const hf* src) {
    unsigned d = (unsigned)__cvta_generic_to_shared(dst);
    asm volatile("cp.async.cg.shared.global [%0], [%1], 16;" :: "r"(d), "l"(src));
}

// ------ fp16 GEMM: 128x128x32, 3-stage cp.async, ldmatrix ------------------
// EPI: 0 = bias -> fp16, 1 = bias+GELU(fast) -> fp16,
//      4 = bias + (res*sig+mu) -> fp16,  5 = bias + (res*sig+mu) -> f32
#define SSTG 5120

template <int EPI>
__global__ void __launch_bounds__(256, 2)
k_mma2(const hf* __restrict__ A, const hf* __restrict__ Wt,
       const float* __restrict__ bias, const hf* __restrict__ res,
       const float2* __restrict__ scv, void* __restrict__ outv,
       int M, int N, int K) {
    extern __shared__ hf smem[];
    hf* sA = smem;
    hf* sB = smem + 3 * SSTG;

    int tid  = threadIdx.x;
    int lane = tid & 31, warp = tid >> 5;
    int wm = warp >> 2, wn = warp & 3;
    int gid = lane >> 2, tg = lane & 3;
    int t8 = lane >> 3, r8 = lane & 7;
    int bn = blockIdx.x, bm = blockIdx.y;

    const hf* Ab = A  + (size_t)bm * 128 * K;
    const hf* Bb = Wt + (size_t)bn * 128 * K;

    int lrow = tid >> 1;
    int lc0 = (tid & 1) * 2;

    float acc[4][4][4];
    #pragma unroll
    for (int i = 0; i < 4; i++)
        #pragma unroll
        for (int j = 0; j < 4; j++)
            #pragma unroll
            for (int r = 0; r < 4; r++) acc[i][j][r] = 0.f;

    int nst = K >> 5;
    #pragma unroll
    for (int p = 0; p < 2; p++) {
        int k0 = p << 5;
        #pragma unroll
        for (int j = 0; j < 2; j++) {
            int c = lc0 + j;
            cpa16(sA + p * SSTG + lrow * 40 + c * 8, Ab + (size_t)lrow * K + k0 + c * 8);
            cpa16(sB + p * SSTG + lrow * 40 + c * 8, Bb + (size_t)lrow * K + k0 + c * 8);
        }
        asm volatile("cp.async.commit_group;");
    }

    for (int st = 0; st < nst; st++) {
        if (st + 1 < nst) asm volatile("cp.async.wait_group 1;");
        else              asm volatile("cp.async.wait_group 0;");
        __syncthreads();

        if (st + 2 < nst) {
            int k0 = (st + 2) << 5;
            int sp = (st + 2) % 3;
            #pragma unroll
            for (int j = 0; j < 2; j++) {
                int c = lc0 + j;
                cpa16(sA + sp * SSTG + lrow * 40 + c * 8, Ab + (size_t)lrow * K + k0 + c * 8);
                cpa16(sB + sp * SSTG + lrow * 40 + c * 8, Bb + (size_t)lrow * K + k0 + c * 8);
            }
            asm volatile("cp.async.commit_group;");
        } else {
            asm volatile("cp.async.commit_group;");
        }

        const hf* As_ = sA + (st % 3) * SSTG;
        const hf* Bs_ = sB + (st % 3) * SSTG;
        #pragma unroll
        for (int ks = 0; ks < 2; ks++) {
            int kk = ks * 16;
            unsigned af[4][4];
            #pragma unroll
            for (int mt = 0; mt < 4; mt++)
                ldmx4(af[mt], As_ + (wm * 64 + mt * 16 + (t8 & 1) * 8 + r8) * 40 + kk + (t8 >> 1) * 8);
            unsigned bfx[4][2];
            #pragma unroll
            for (int np = 0; np < 2; np++) {
                unsigned b4[4];
                ldmx4(b4, Bs_ + (wn * 32 + np * 16 + (t8 >> 1) * 8 + r8) * 40 + kk + (t8 & 1) * 8);
                bfx[np * 2][0] = b4[0]; bfx[np * 2][1] = b4[1];
                bfx[np * 2 + 1][0] = b4[2]; bfx[np * 2 + 1][1] = b4[3];
            }
            #pragma unroll
            for (int mt = 0; mt < 4; mt++)
                #pragma unroll
                for (int nt = 0; nt < 4; nt++)
                    mma16816(acc[mt][nt], af[mt], bfx[nt][0], bfx[nt][1]);
        }
    }

    float* outf = (float*)outv;
    hf*    outh = (hf*)outv;
    #pragma unroll
    for (int mt = 0; mt < 4; mt++) {
        int row0 = bm * 128 + wm * 64 + mt * 16 + gid;
        #pragma unroll
        for (int h = 0; h < 2; h++) {
            int row = row0 + h * 8;
            float mu = 0.f, sg = 0.f;
            if (EPI >= 4) { float2 sc = scv[row]; mu = sc.x; sg = sc.y; }
            #pragma unroll
            for (int nt = 0; nt < 4; nt++) {
                int col = bn * 128 + wn * 32 + nt * 8 + tg * 2;
                size_t off = (size_t)row * N + col;
                float v0 = acc[mt][nt][h * 2 + 0] + bias[col];
                float v1 = acc[mt][nt][h * 2 + 1] + bias[col + 1];
                if (EPI == 1) {
                    v0 = gelu_fast(v0);
                    v1 = gelu_fast(v1);
                }
                if (EPI >= 4) {
                    float2 rf = __half22float2(*(const __half2*)(res + off));
                    v0 += rf.x * sg + mu;
                    v1 += rf.y * sg + mu;
                }
                if (EPI == 5) {
                    float2 ov; ov.x = v0; ov.y = v1;
                    *(float2*)(outf + off) = ov;
                } else {
                    *(__half2*)(outh + off) = __floats2half2_rn(v0, v1);
                }
            }
        }
    }
}

// ---------------- tensor-core attention: block = (window, head) ------------
// softmax runs in exp2 domain (log2e folded into Q projection)
__global__ void __launch_bounds__(128)
k_attn2(const hf* __restrict__ qkv, hf* __restrict__ o) {
    __shared__ hf Qs[64 * 40];
    __shared__ hf Ks[64 * 40];
    __shared__ hf Vt[32 * 72];
    int w = blockIdx.x, hd = blockIdx.y;
    int tid = threadIdx.x, lane = tid & 31, warp = tid >> 5;
    int gid = lane >> 2, tg = lane & 3;
    int t8 = lane >> 3, r8 = lane & 7;

    const hf* base = qkv + (size_t)w * 64 * NQKV + hd * 32;
    // vectorized Q/K loads
    #pragma unroll
    for (int t4 = tid; t4 < 512; t4 += 128) {
        int mtx = t4 >> 8;
        int r = (t4 >> 2) & 63;
        int c = (t4 & 3) * 8;
        uint4 v = *(const uint4*)(base + (size_t)r * NQKV + mtx * CD + c);
        *(uint4*)((mtx ? Ks : Qs) + r * 40 + c) = v;
    }
    // V: vectorized load (uint4), scalar transpose scatter
    #pragma unroll
    for (int t4 = tid; t4 < 256; t4 += 128) {
        int r = t4 >> 2;            // row l: 0..63
        int c = (t4 & 3) * 8;       // d: 0,8,16,24
        uint4 v = *(const uint4*)(base + (size_t)r * NQKV + 2 * CD + c);
        hf tmp[8];
        *(uint4*)tmp = v;
        #pragma unroll
        for (int e = 0; e < 8; e++) Vt[(c + e) * 72 + r] = tmp[e];
    }
    __syncthreads();

    unsigned aq[2][4];
    #pragma unroll
    for (int ks = 0; ks < 2; ks++)
        ldmx4(aq[ks], Qs + (warp * 16 + (t8 & 1) * 8 + r8) * 40 + ks * 16 + (t8 >> 1) * 8);

    float acc[8][4];
    #pragma unroll
    for (int i = 0; i < 8; i++)
        #pragma unroll
        for (int j = 0; j < 4; j++) acc[i][j] = 0.f;

    #pragma unroll
    for (int ks = 0; ks < 2; ks++) {
        #pragma unroll
        for (int np = 0; np < 4; np++) {
            unsigned b4[4];
            ldmx4(b4, Ks + (np * 16 + (t8 >> 1) * 8 + r8) * 40 + ks * 16 + (t8 & 1) * 8);
            mma16816(acc[np * 2],     aq[ks], b4[0], b4[1]);
            mma16816(acc[np * 2 + 1], aq[ks], b4[2], b4[3]);
        }
    }

    float mx0 = -1e30f, mx1 = -1e30f;
    #pragma unroll
    for (int nt = 0; nt < 8; nt++) {
        mx0 = fmaxf(mx0, fmaxf(acc[nt][0], acc[nt][1]));
        mx1 = fmaxf(mx1, fmaxf(acc[nt][2], acc[nt][3]));
    }
    mx0 = fmaxf(mx0, __shfl_xor_sync(0xffffffffu, mx0, 1));
    mx0 = fmaxf(mx0, __shfl_xor_sync(0xffffffffu, mx0, 2));
    mx1 = fmaxf(mx1, __shfl_xor_sync(0xffffffffu, mx1, 1));
    mx1 = fmaxf(mx1, __shfl_xor_sync(0xffffffffu, mx1, 2));

    float s0 = 0.f, s1 = 0.f;
    #pragma unroll
    for (int nt = 0; nt < 8; nt++) {
        acc[nt][0] = ex2f(acc[nt][0] - mx0); s0 += acc[nt][0];
        acc[nt][1] = ex2f(acc[nt][1] - mx0); s0 += acc[nt][1];
        acc[nt][2] = ex2f(acc[nt][2] - mx1); s1 += acc[nt][2];
        acc[nt][3] = ex2f(acc[nt][3] - mx1); s1 += acc[nt][3];
    }
    s0 += __shfl_xor_sync(0xffffffffu, s0, 1);
    s0 += __shfl_xor_sync(0xffffffffu, s0, 2);
    s1 += __shfl_xor_sync(0xffffffffu, s1, 1);
    s1 += __shfl_xor_sync(0xffffffffu, s1, 2);
    float inv0 = rcpf(s0), inv1 = rcpf(s1);

    unsigned pa[4][4];
    #pragma unroll
    for (int j = 0; j < 4; j++) {
        __half2 p0 = __floats2half2_rn(acc[2*j][0]*inv0,   acc[2*j][1]*inv0);
        __half2 p1 = __floats2half2_rn(acc[2*j][2]*inv1,   acc[2*j][3]*inv1);
        __half2 p2 = __floats2half2_rn(acc[2*j+1][0]*inv0, acc[2*j+1][1]*inv0);
        __half2 p3 = __floats2half2_rn(acc[2*j+1][2]*inv1, acc[2*j+1][3]*inv1);
        pa[j][0] = *(unsigned*)&p0; pa[j][1] = *(unsigned*)&p1;
        pa[j][2] = *(unsigned*)&p2; pa[j][3] = *(unsigned*)&p3;
    }

    float o4[4][4];
    #pragma unroll
    for (int i = 0; i < 4; i++)
        #pragma unroll
        for (int j = 0; j < 4; j++) o4[i][j] = 0.f;

    #pragma unroll
    for (int j = 0; j < 4; j++) {
        #pragma unroll
        for (int np = 0; np < 2; np++) {
            unsigned b4[4];
            ldmx4(b4, Vt + (np * 16 + (t8 >> 1) * 8 + r8) * 72 + j * 16 + (t8 & 1) * 8);
            mma16816(o4[np * 2],     pa[j], b4[0], b4[1]);
            mma16816(o4[np * 2 + 1], pa[j], b4[2], b4[3]);
        }
    }

    int r0 = w * 64 + warp * 16 + gid;
    #pragma unroll
    for (int nt = 0; nt < 4; nt++) {
        int col = hd * 32 + nt * 8 + tg * 2;
        *(__half2*)(o + (size_t)r0 * CD + col)       = __floats2half2_rn(o4[nt][0], o4[nt][1]);
        *(__half2*)(o + (size_t)(r0 + 8) * CD + col) = __floats2half2_rn(o4[nt][2], o4[nt][3]);
    }
}

// -------- nout-LN + reverse-window + residual + LN2: warp per token --------
__global__ void __launch_bounds__(256)
k_lnout2(const hf* __restrict__ ores, const float* __restrict__ x,
         const float* __restrict__ gno, const float* __restrict__ bno,
         hf* __restrict__ u2, float2* __restrict__ sc2) {
    int wid = threadIdx.x >> 5, lane = threadIdx.x & 31;
    int t = blockIdx.x * 8 + wid;
    size_t src = (size_t)t * CD;
    int xrow = t_to_xrow(t);
    size_t dst = (size_t)xrow * CD;

    float4 ov[3];
    float s = 0.f, sq = 0.f;
    #pragma unroll
    for (int j = 0; j < 3; j++) {
        uint2 pk = *(const uint2*)(ores + src + j * 128 + lane * 4);
        float2 lo = __half22float2(*(const __half2*)&pk.x);
        float2 hi = __half22float2(*(const __half2*)&pk.y);
        ov[j].x = lo.x; ov[j].y = lo.y; ov[j].z = hi.x; ov[j].w = hi.y;
        s += ov[j].x + ov[j].y + ov[j].z + ov[j].w;
        sq += ov[j].x * ov[j].x + ov[j].y * ov[j].y + ov[j].z * ov[j].z + ov[j].w * ov[j].w;
    }
    wreduce2(s, sq);
    float m = s * (1.f / CD);
    float r = rsqrtf(sq * (1.f / CD) - m * m + 1e-5f);

    float4 xv[3];
    s = 0.f; sq = 0.f;
    #pragma unroll
    for (int j = 0; j < 3; j++) {
        int c = j * 128 + lane * 4;
        float4 g = *(const float4*)(gno + c);
        float4 b = *(const float4*)(bno + c);
        float4 xr = *(const float4*)(x + dst + c);
        xv[j].x = xr.x + (ov[j].x - m) * r * g.x + b.x;
        xv[j].y = xr.y + (ov[j].y - m) * r * g.y + b.y;
        xv[j].z = xr.z + (ov[j].z - m) * r * g.z + b.z;
        xv[j].w = xr.w + (ov[j].w - m) * r * g.w + b.w;
        s += xv[j].x + xv[j].y + xv[j].z + xv[j].w;
        sq += xv[j].x * xv[j].x + xv[j].y * xv[j].y + xv[j].z * xv[j].z + xv[j].w * xv[j].w;
    }
    wreduce2(s, sq);
    float m2 = s * (1.f / CD);
    float r2 = rsqrtf(sq * (1.f / CD) - m2 * m2 + 1e-5f);

    if (lane == 0) sc2[xrow] = make_float2(m2, 1.f / r2);

    #pragma unroll
    for (int j = 0; j < 3; j++) {
        int c = j * 128 + lane * 4;
        *(__half2*)(u2 + dst + c)     = __floats2half2_rn((xv[j].x - m2) * r2, (xv[j].y - m2) * r2);
        *(__half2*)(u2 + dst + c + 2) = __floats2half2_rn((xv[j].z - m2) * r2, (xv[j].w - m2) * r2);
    }
}

// ---------------- host launcher --------------------------------------------
extern "C" void kernel_launch(void* const* d_in, const int* in_sizes, int n_in,
                              void* d_out, int out_size) {
    const float* x   = (const float*)d_in[0];
    const float* g1  = (const float*)d_in[1];
    const float* b1  = (const float*)d_in[2];
    const float* gq  = (const float*)d_in[3];
    const float* bq  = (const float*)d_in[4];
    const float* gk  = (const float*)d_in[5];
    const float* bk  = (const float*)d_in[6];
    const float* gv  = (const float*)d_in[7];
    const float* bv  = (const float*)d_in[8];
    const float* gno = (const float*)d_in[9];
    const float* bno = (const float*)d_in[10];
    const float* ipw = (const float*)d_in[11];
    const float* ipb = (const float*)d_in[12];
    const float* opw = (const float*)d_in[13];
    const float* opb = (const float*)d_in[14];
    const float* g2n = (const float*)d_in[15];
    const float* b2n = (const float*)d_in[16];
    const float* w1  = (const float*)d_in[17];
    const float* b1f = (const float*)d_in[18];
    const float* w2  = (const float*)d_in[19];
    const float* b2f = (const float*)d_in[20];

    int B = in_sizes[0] / (64 * 64 * CD);
    int T = B * 64 * 64;
    int nW = B * 64;

    float *bqkv, *b1p;
    float2 *sc1, *sc2;
    hf *u, *qkv, *obf, *ores, *u2, *hbf, *wqkv, *opwb, *w1b, *w2b;
    cudaGetSymbolAddress((void**)&u,    g_u);
    cudaGetSymbolAddress((void**)&qkv,  g_qkv);
    cudaGetSymbolAddress((void**)&obf,  g_obf);
    cudaGetSymbolAddress((void**)&ores, g_ores);
    cudaGetSymbolAddress((void**)&u2,   g_u2);
    cudaGetSymbolAddress((void**)&hbf,  g_hbf);
    cudaGetSymbolAddress((void**)&sc1,  g_sc1);
    cudaGetSymbolAddress((void**)&sc2,  g_sc2);
    cudaGetSymbolAddress((void**)&wqkv, g_wqkv);
    cudaGetSymbolAddress((void**)&bqkv, g_bqkv);
    cudaGetSymbolAddress((void**)&opwb, g_opw);
    cudaGetSymbolAddress((void**)&w1b,  g_w1);
    cudaGetSymbolAddress((void**)&b1p,  g_b1p);
    cudaGetSymbolAddress((void**)&w2b,  g_w2);

    const int dynsmem = 3 * 2 * SSTG * (int)sizeof(hf);   // 61440
    cudaFuncSetAttribute(k_mma2<0>, cudaFuncAttributeMaxDynamicSharedMemorySize, dynsmem);
    cudaFuncSetAttribute(k_mma2<1>, cudaFuncAttributeMaxDynamicSharedMemorySize, dynsmem);
    cudaFuncSetAttribute(k_mma2<4>, cudaFuncAttributeMaxDynamicSharedMemorySize, dynsmem);
    cudaFuncSetAttribute(k_mma2<5>, cudaFuncAttributeMaxDynamicSharedMemorySize, dynsmem);

    // side stream + events for weight-prep overlap
    static cudaStream_t s2 = nullptr;
    static cudaEvent_t evFork = nullptr, evJoin = nullptr;
    if (!s2) {
        cudaStreamCreateWithFlags(&s2, cudaStreamNonBlocking);
        cudaEventCreateWithFlags(&evFork, cudaEventDisableTiming);
        cudaEventCreateWithFlags(&evJoin, cudaEventDisableTiming);
    }

    cudaEventRecord(evFork, 0);
    cudaStreamWaitEvent(s2, evFork, 0);
    k_wqkv<<<NQKV, 128, 0, s2>>>(ipw, ipb, gq, bq, gk, bk, gv, bv, wqkv, bqkv);
    k_w1p<<<FFD, 128, 0, s2>>>(w1, b1f, g2n, b2n, w1b, b1p);
    k_f2h<<<(CD*CD  + 255) / 256, 256, 0, s2>>>(opw, opwb, CD*CD);
    k_f2h<<<(CD*FFD + 255) / 256, 256, 0, s2>>>(w2,  w2b,  CD*FFD);
    cudaEventRecord(evJoin, s2);

    // 1) LN1 + window partition — overlaps weight prep
    k_prep2<<<T / 8, 256>>>(x, g1, b1, u, sc1);

    cudaStreamWaitEvent(0, evJoin, 0);

    // 2) fused QKV projection
    dim3 thr(256);
    k_mma2<0><<<dim3(NQKV/128, T/128), thr, dynsmem>>>(u, wqkv, bqkv, nullptr, nullptr, qkv, T, NQKV, CD);

    // 3) tensor-core windowed attention (exp2-domain softmax)
    k_attn2<<<dim3(nW, 12), 128>>>(qkv, obf);

    // 4) out_proj + residual win = u*sig+mu -> ores (fp16)
    k_mma2<4><<<dim3(CD/128, T/128), thr, dynsmem>>>(obf, opwb, opb, u, sc1, ores, T, CD, CD);

    // 5) nout-LN + reverse window + residual + LN2
    k_lnout2<<<T / 8, 256>>>(ores, x, gno, bno, u2, sc2);

    // 6) MLP (fast-tanh GELU in epilogue)
    k_mma2<1><<<dim3(FFD/128, T/128), thr, dynsmem>>>(u2, w1b, b1p, nullptr, nullptr, hbf, T, FFD, CD);
    k_mma2<5><<<dim3(CD/128, T/128), thr, dynsmem>>>(hbf, w2b, b2f, u2, sc2, (float*)d_out, T, CD, FFD);
}

// round 17
// speedup vs baseline: 1.1502x; 1.0028x over previous
#include <cuda_runtime.h>
#include <cuda_fp16.h>
#include <math.h>

#define CD 384
#define FFD 1536
#define NQKV 1152
#define TMAX (32*64*64)

typedef __half hf;

// ---------------- scratch ----------------
__device__ hf     g_u   [(size_t)TMAX * CD];
__device__ hf     g_qkv [(size_t)TMAX * NQKV];
__device__ hf     g_obf [(size_t)TMAX * CD];
__device__ hf     g_ores[(size_t)TMAX * CD];
__device__ hf     g_u2  [(size_t)TMAX * CD];
__device__ hf     g_hbf [(size_t)TMAX * FFD];
__device__ float2 g_sc1 [TMAX];
__device__ float2 g_sc2 [TMAX];
__device__ hf     g_wqkv[NQKV * CD];
__device__ float  g_bqkv[NQKV];
__device__ hf     g_opw [CD * CD];
__device__ hf     g_w1  [FFD * CD];
__device__ float  g_b1p [FFD];
__device__ hf     g_w2  [CD * FFD];

// ---------------- fast math helpers ----------------
__device__ __forceinline__ float gelu_fast(float v) {
    float inner = 0.79788456080286536f * fmaf(0.044715f * v * v, v, v);
    float t;
    asm("tanh.approx.f32 %0, %1;" : "=f"(t) : "f"(inner));
    return 0.5f * v * (1.f + t);
}
__device__ __forceinline__ float ex2f(float v) {
    float r;
    asm("ex2.approx.f32 %0, %1;" : "=f"(r) : "f"(v));
    return r;
}
__device__ __forceinline__ float rcpf(float v) {
    float r;
    asm("rcp.approx.f32 %0, %1;" : "=f"(r) : "f"(v));
    return r;
}

// ---------------- small helpers ----------------
__global__ void k_f2h(const float* __restrict__ s, hf* __restrict__ d, int n) {
    int i = blockIdx.x * blockDim.x + threadIdx.x;
    if (i < n) d[i] = __float2half(s[i]);
}

__global__ void k_wqkv(const float* __restrict__ ipw, const float* __restrict__ ipb,
                       const float* __restrict__ gq, const float* __restrict__ bq,
                       const float* __restrict__ gk, const float* __restrict__ bk,
                       const float* __restrict__ gv, const float* __restrict__ bv,
                       hf* __restrict__ Wo, float* __restrict__ bo) {
    __shared__ float sm[4];
    int n = blockIdx.x, tid = threadIdx.x;
    int s = n / CD;
    const float* g = (s == 0) ? gq : (s == 1) ? gk : gv;
    const float* bb = (s == 0) ? bq : (s == 1) ? bk : bv;
    // Q scale: 1/sqrt(32) * log2(e) (softmax in exp2 domain)
    float scl = (s == 0) ? 0.25506977234862308f : 1.f;
    float part = 0.f;
    for (int c = tid; c < CD; c += 128) {
        float wv = ipw[(size_t)n * CD + c];
        part += wv * bb[c];
        Wo[(size_t)n * CD + c] = __float2half(wv * g[c] * scl);
    }
    #pragma unroll
    for (int o = 16; o > 0; o >>= 1) part += __shfl_down_sync(0xffffffffu, part, o);
    if ((tid & 31) == 0) sm[tid >> 5] = part;
    __syncthreads();
    if (tid == 0) bo[n] = (ipb[n] + sm[0] + sm[1] + sm[2] + sm[3]) * scl;
}

__global__ void k_w1p(const float* __restrict__ w1, const float* __restrict__ b1,
                      const float* __restrict__ g2, const float* __restrict__ b2,
                      hf* __restrict__ Wo, float* __restrict__ bo) {
    __shared__ float sm[4];
    int n = blockIdx.x, tid = threadIdx.x;
    float part = 0.f;
    for (int c = tid; c < CD; c += 128) {
        float wv = w1[(size_t)n * CD + c];
        part += wv * b2[c];
        Wo[(size_t)n * CD + c] = __float2half(wv * g2[c]);
    }
    #pragma unroll
    for (int o = 16; o > 0; o >>= 1) part += __shfl_down_sync(0xffffffffu, part, o);
    if ((tid & 31) == 0) sm[tid >> 5] = part;
    __syncthreads();
    if (tid == 0) bo[n] = b1[n] + sm[0] + sm[1] + sm[2] + sm[3];
}

__device__ __forceinline__ int t_to_xrow(int t) {
    int w = t >> 6, l = t & 63;
    int b = w >> 6, wi = w & 63;
    int wy = wi >> 3, wx = wi & 7;
    int iy = l >> 3, ix = l & 7;
    return b * 4096 + (wy * 8 + iy) * 64 + wx * 8 + ix;
}

__device__ __forceinline__ void wreduce2(float& s0, float& s1) {
    #pragma unroll
    for (int o = 16; o > 0; o >>= 1) {
        s0 += __shfl_xor_sync(0xffffffffu, s0, o);
        s1 += __shfl_xor_sync(0xffffffffu, s1, o);
    }
}

// ---------------- LN1 + window partition: warp per token -------------------
__global__ void __launch_bounds__(256)
k_prep2(const float* __restrict__ x,
        const float* __restrict__ g1, const float* __restrict__ b1,
        hf* __restrict__ u, float2* __restrict__ sc1) {
    int wid = threadIdx.x >> 5, lane = threadIdx.x & 31;
    int t = blockIdx.x * 8 + wid;
    size_t src = (size_t)t_to_xrow(t) * CD;
    size_t dst = (size_t)t * CD;

    float4 xv[3];
    float s = 0.f, sq = 0.f;
    #pragma unroll
    for (int j = 0; j < 3; j++) {
        xv[j] = *(const float4*)(x + src + j * 128 + lane * 4);
        s += xv[j].x + xv[j].y + xv[j].z + xv[j].w;
        sq += xv[j].x * xv[j].x + xv[j].y * xv[j].y + xv[j].z * xv[j].z + xv[j].w * xv[j].w;
    }
    wreduce2(s, sq);
    float m = s * (1.f / CD);
    float r = rsqrtf(sq * (1.f / CD) - m * m + 1e-5f);

    float4 wv[3];
    s = 0.f; sq = 0.f;
    #pragma unroll
    for (int j = 0; j < 3; j++) {
        int c = j * 128 + lane * 4;
        float4 g = *(const float4*)(g1 + c);
        float4 b = *(const float4*)(b1 + c);
        wv[j].x = (xv[j].x - m) * r * g.x + b.x;
        wv[j].y = (xv[j].y - m) * r * g.y + b.y;
        wv[j].z = (xv[j].z - m) * r * g.z + b.z;
        wv[j].w = (xv[j].w - m) * r * g.w + b.w;
        s += wv[j].x + wv[j].y + wv[j].z + wv[j].w;
        sq += wv[j].x * wv[j].x + wv[j].y * wv[j].y + wv[j].z * wv[j].z + wv[j].w * wv[j].w;
    }
    wreduce2(s, sq);
    float m2 = s * (1.f / CD);
    float r2 = rsqrtf(sq * (1.f / CD) - m2 * m2 + 1e-5f);

    if (lane == 0) sc1[t] = make_float2(m2, 1.f / r2);

    #pragma unroll
    for (int j = 0; j < 3; j++) {
        int c = j * 128 + lane * 4;
        *(__half2*)(u + dst + c)     = __floats2half2_rn((wv[j].x - m2) * r2, (wv[j].y - m2) * r2);
        *(__half2*)(u + dst + c + 2) = __floats2half2_rn((wv[j].z - m2) * r2, (wv[j].w - m2) * r2);
    }
}

// ---------------- ldmatrix / mma wrappers ----------------
__device__ __forceinline__ void ldmx4(unsigned* r, const hf* p) {
    unsigned a = (unsigned)__cvta_generic_to_shared(p);
    asm volatile("ldmatrix.sync.aligned.m8n8.x4.shared.b16 {%0,%1,%2,%3}, [%4];"
                 : "=r"(r[0]), "=r"(r[1]), "=r"(r[2]), "=r"(r[3]) : "r"(a));
}
__device__ __forceinline__ void ldmx4t(unsigned* r, const hf* p) {
    unsigned a = (unsigned)__cvta_generic_to_shared(p);
    asm volatile("ldmatrix.sync.aligned.m8n8.x4.trans.shared.b16 {%0,%1,%2,%3}, [%4];"
                 : "=r"(r[0]), "=r"(r[1]), "=r"(r[2]), "=r"(r[3]) : "r"(a));
}
__device__ __forceinline__ void mma16816(float* c, const unsigned* a, unsigned b0, unsigned b1) {
    asm volatile(
        "mma.sync.aligned.m16n8k16.row.col.f32.f16.f16.f32 "
        "{%0,%1,%2,%3}, {%4,%5,%6,%7}, {%8,%9}, {%0,%1,%2,%3};"
        : "+f"(c[0]), "+f"(c[1]), "+f"(c[2]), "+f"(c[3])
        : "r"(a[0]), "r"(a[1]), "r"(a[2]), "r"(a[3]), "r"(b0), "r"(b1));
}
__device__ __forceinline__ void cpa16(hf* dst, const hf* src) {
    unsigned d = (unsigned)__cvta_generic_to_shared(dst);
    asm volatile("cp.async.cg.shared.global [%0], [%1], 16;" :: "r"(d), "l"(src));
}

// ------ fp16 GEMM: 128x128x32, 3-stage cp.async, ldmatrix ------------------
// EPI: 0 = bias -> fp16, 1 = bias+GELU(fast) -> fp16,
//      4 = bias + (res*sig+mu) -> fp16,  5 = bias + (res*sig+mu) -> f32
#define SSTG 5120

template <int EPI>
__global__ void __launch_bounds__(256, 2)
k_mma2(const hf* __restrict__ A, const hf* __restrict__ Wt,
       const float* __restrict__ bias, const hf* __restrict__ res,
       const float2* __restrict__ scv, void* __restrict__ outv,
       int M, int N, int K) {
    extern __shared__ hf smem[];
    hf* sA = smem;
    hf* sB = smem + 3 * SSTG;

    int tid  = threadIdx.x;
    int lane = tid & 31, warp = tid >> 5;
    int wm = warp >> 2, wn = warp & 3;
    int gid = lane >> 2, tg = lane & 3;
    int t8 = lane >> 3, r8 = lane & 7;
    int bn = blockIdx.x, bm = blockIdx.y;

    const hf* Ab = A  + (size_t)bm * 128 * K;
    const hf* Bb = Wt + (size_t)bn * 128 * K;

    int lrow = tid >> 1;
    int lc0 = (tid & 1) * 2;

    float acc[4][4][4];
    #pragma unroll
    for (int i = 0; i < 4; i++)
        #pragma unroll
        for (int j = 0; j < 4; j++)
            #pragma unroll
            for (int r = 0; r < 4; r++) acc[i][j][r] = 0.f;

    int nst = K >> 5;
    #pragma unroll
    for (int p = 0; p < 2; p++) {
        int k0 = p << 5;
        #pragma unroll
        for (int j = 0; j < 2; j++) {
            int c = lc0 + j;
            cpa16(sA + p * SSTG + lrow * 40 + c * 8, Ab + (size_t)lrow * K + k0 + c * 8);
            cpa16(sB + p * SSTG + lrow * 40 + c * 8, Bb + (size_t)lrow * K + k0 + c * 8);
        }
        asm volatile("cp.async.commit_group;");
    }

    for (int st = 0; st < nst; st++) {
        if (st + 1 < nst) asm volatile("cp.async.wait_group 1;");
        else              asm volatile("cp.async.wait_group 0;");
        __syncthreads();

        if (st + 2 < nst) {
            int k0 = (st + 2) << 5;
            int sp = (st + 2) % 3;
            #pragma unroll
            for (int j = 0; j < 2; j++) {
                int c = lc0 + j;
                cpa16(sA + sp * SSTG + lrow * 40 + c * 8, Ab + (size_t)lrow * K + k0 + c * 8);
                cpa16(sB + sp * SSTG + lrow * 40 + c * 8, Bb + (size_t)lrow * K + k0 + c * 8);
            }
            asm volatile("cp.async.commit_group;");
        } else {
            asm volatile("cp.async.commit_group;");
        }

        const hf* As_ = sA + (st % 3) * SSTG;
        const hf* Bs_ = sB + (st % 3) * SSTG;
        #pragma unroll
        for (int ks = 0; ks < 2; ks++) {
            int kk = ks * 16;
            unsigned af[4][4];
            #pragma unroll
            for (int mt = 0; mt < 4; mt++)
                ldmx4(af[mt], As_ + (wm * 64 + mt * 16 + (t8 & 1) * 8 + r8) * 40 + kk + (t8 >> 1) * 8);
            unsigned bfx[4][2];
            #pragma unroll
            for (int np = 0; np < 2; np++) {
                unsigned b4[4];
                ldmx4(b4, Bs_ + (wn * 32 + np * 16 + (t8 >> 1) * 8 + r8) * 40 + kk + (t8 & 1) * 8);
                bfx[np * 2][0] = b4[0]; bfx[np * 2][1] = b4[1];
                bfx[np * 2 + 1][0] = b4[2]; bfx[np * 2 + 1][1] = b4[3];
            }
            #pragma unroll
            for (int mt = 0; mt < 4; mt++)
                #pragma unroll
                for (int nt = 0; nt < 4; nt++)
                    mma16816(acc[mt][nt], af[mt], bfx[nt][0], bfx[nt][1]);
        }
    }

    float* outf = (float*)outv;
    hf*    outh = (hf*)outv;
    #pragma unroll
    for (int mt = 0; mt < 4; mt++) {
        int row0 = bm * 128 + wm * 64 + mt * 16 + gid;
        #pragma unroll
        for (int h = 0; h < 2; h++) {
            int row = row0 + h * 8;
            float mu = 0.f, sg = 0.f;
            if (EPI >= 4) { float2 sc = scv[row]; mu = sc.x; sg = sc.y; }
            #pragma unroll
            for (int nt = 0; nt < 4; nt++) {
                int col = bn * 128 + wn * 32 + nt * 8 + tg * 2;
                size_t off = (size_t)row * N + col;
                float2 bi = *(const float2*)(bias + col);
                float v0 = acc[mt][nt][h * 2 + 0] + bi.x;
                float v1 = acc[mt][nt][h * 2 + 1] + bi.y;
                if (EPI == 1) {
                    v0 = gelu_fast(v0);
                    v1 = gelu_fast(v1);
                }
                if (EPI >= 4) {
                    float2 rf = __half22float2(*(const __half2*)(res + off));
                    v0 += rf.x * sg + mu;
                    v1 += rf.y * sg + mu;
                }
                if (EPI == 5) {
                    float2 ov; ov.x = v0; ov.y = v1;
                    *(float2*)(outf + off) = ov;
                } else {
                    *(__half2*)(outh + off) = __floats2half2_rn(v0, v1);
                }
            }
        }
    }
}

// ---------------- tensor-core attention: block = (window, head) ------------
// exp2-domain softmax; V kept row-major, transposed by ldmatrix.trans
__global__ void __launch_bounds__(128)
k_attn2(const hf* __restrict__ qkv, hf* __restrict__ o) {
    __shared__ hf Qs[64 * 40];
    __shared__ hf Ks[64 * 40];
    __shared__ hf Vs[64 * 40];   // [l][d], pitch 40 (80B rows, 16B aligned)
    int w = blockIdx.x, hd = blockIdx.y;
    int tid = threadIdx.x, lane = tid & 31, warp = tid >> 5;
    int gid = lane >> 2, tg = lane & 3;
    int t8 = lane >> 3, r8 = lane & 7;

    const hf* base = qkv + (size_t)w * 64 * NQKV + hd * 32;
    // vectorized Q/K/V loads: 768 uint4 tasks (Q:0..255, K:256..511, V:512..767)
    #pragma unroll
    for (int t4 = tid; t4 < 768; t4 += 128) {
        int mtx = t4 >> 8;                 // 0=Q, 1=K, 2=V
        int r = (t4 >> 2) & 63;
        int c = (t4 & 3) * 8;
        uint4 v = *(const uint4*)(base + (size_t)r * NQKV + mtx * CD + c);
        hf* dst = (mtx == 0) ? Qs : (mtx == 1) ? Ks : Vs;
        *(uint4*)(dst + r * 40 + c) = v;
    }
    __syncthreads();

    unsigned aq[2][4];
    #pragma unroll
    for (int ks = 0; ks < 2; ks++)
        ldmx4(aq[ks], Qs + (warp * 16 + (t8 & 1) * 8 + r8) * 40 + ks * 16 + (t8 >> 1) * 8);

    float acc[8][4];
    #pragma unroll
    for (int i = 0; i < 8; i++)
        #pragma unroll
        for (int j = 0; j < 4; j++) acc[i][j] = 0.f;

    #pragma unroll
    for (int ks = 0; ks < 2; ks++) {
        #pragma unroll
        for (int np = 0; np < 4; np++) {
            unsigned b4[4];
            ldmx4(b4, Ks + (np * 16 + (t8 >> 1) * 8 + r8) * 40 + ks * 16 + (t8 & 1) * 8);
            mma16816(acc[np * 2],     aq[ks], b4[0], b4[1]);
            mma16816(acc[np * 2 + 1], aq[ks], b4[2], b4[3]);
        }
    }

    float mx0 = -1e30f, mx1 = -1e30f;
    #pragma unroll
    for (int nt = 0; nt < 8; nt++) {
        mx0 = fmaxf(mx0, fmaxf(acc[nt][0], acc[nt][1]));
        mx1 = fmaxf(mx1, fmaxf(acc[nt][2], acc[nt][3]));
    }
    mx0 = fmaxf(mx0, __shfl_xor_sync(0xffffffffu, mx0, 1));
    mx0 = fmaxf(mx0, __shfl_xor_sync(0xffffffffu, mx0, 2));
    mx1 = fmaxf(mx1, __shfl_xor_sync(0xffffffffu, mx1, 1));
    mx1 = fmaxf(mx1, __shfl_xor_sync(0xffffffffu, mx1, 2));

    float s0 = 0.f, s1 = 0.f;
    #pragma unroll
    for (int nt = 0; nt < 8; nt++) {
        acc[nt][0] = ex2f(acc[nt][0] - mx0); s0 += acc[nt][0];
        acc[nt][1] = ex2f(acc[nt][1] - mx0); s0 += acc[nt][1];
        acc[nt][2] = ex2f(acc[nt][2] - mx1); s1 += acc[nt][2];
        acc[nt][3] = ex2f(acc[nt][3] - mx1); s1 += acc[nt][3];
    }
    s0 += __shfl_xor_sync(0xffffffffu, s0, 1);
    s0 += __shfl_xor_sync(0xffffffffu, s0, 2);
    s1 += __shfl_xor_sync(0xffffffffu, s1, 1);
    s1 += __shfl_xor_sync(0xffffffffu, s1, 2);
    float inv0 = rcpf(s0), inv1 = rcpf(s1);

    unsigned pa[4][4];
    #pragma unroll
    for (int j = 0; j < 4; j++) {
        __half2 p0 = __floats2half2_rn(acc[2*j][0]*inv0,   acc[2*j][1]*inv0);
        __half2 p1 = __floats2half2_rn(acc[2*j][2]*inv1,   acc[2*j][3]*inv1);
        __half2 p2 = __floats2half2_rn(acc[2*j+1][0]*inv0, acc[2*j+1][1]*inv0);
        __half2 p3 = __floats2half2_rn(acc[2*j+1][2]*inv1, acc[2*j+1][3]*inv1);
        pa[j][0] = *(unsigned*)&p0; pa[j][1] = *(unsigned*)&p1;
        pa[j][2] = *(unsigned*)&p2; pa[j][3] = *(unsigned*)&p3;
    }

    float o4[4][4];
    #pragma unroll
    for (int i = 0; i < 4; i++)
        #pragma unroll
        for (int j = 0; j < 4; j++) o4[i][j] = 0.f;

    // P @ V: B fragments via ldmatrix.trans of row-major Vs[l][d]
    #pragma unroll
    for (int j = 0; j < 4; j++) {
        #pragma unroll
        for (int np = 0; np < 2; np++) {
            unsigned b4[4];
            ldmx4t(b4, Vs + (j * 16 + (t8 & 1) * 8 + r8) * 40 + np * 16 + (t8 >> 1) * 8);
            mma16816(o4[np * 2],     pa[j], b4[0], b4[1]);
            mma16816(o4[np * 2 + 1], pa[j], b4[2], b4[3]);
        }
    }

    int r0 = w * 64 + warp * 16 + gid;
    #pragma unroll
    for (int nt = 0; nt < 4; nt++) {
        int col = hd * 32 + nt * 8 + tg * 2;
        *(__half2*)(o + (size_t)r0 * CD + col)       = __floats2half2_rn(o4[nt][0], o4[nt][1]);
        *(__half2*)(o + (size_t)(r0 + 8) * CD + col) = __floats2half2_rn(o4[nt][2], o4[nt][3]);
    }
}

// -------- nout-LN + reverse-window + residual + LN2: warp per token --------
__global__ void __launch_bounds__(256)
k_lnout2(const hf* __restrict__ ores, const float* __restrict__ x,
         const float* __restrict__ gno, const float* __restrict__ bno,
         hf* __restrict__ u2, float2* __restrict__ sc2) {
    int wid = threadIdx.x >> 5, lane = threadIdx.x & 31;
    int t = blockIdx.x * 8 + wid;
    size_t src = (size_t)t * CD;
    int xrow = t_to_xrow(t);
    size_t dst = (size_t)xrow * CD;

    float4 ov[3];
    float s = 0.f, sq = 0.f;
    #pragma unroll
    for (int j = 0; j < 3; j++) {
        uint2 pk = *(const uint2*)(ores + src + j * 128 + lane * 4);
        float2 lo = __half22float2(*(const __half2*)&pk.x);
        float2 hi = __half22float2(*(const __half2*)&pk.y);
        ov[j].x = lo.x; ov[j].y = lo.y; ov[j].z = hi.x; ov[j].w = hi.y;
        s += ov[j].x + ov[j].y + ov[j].z + ov[j].w;
        sq += ov[j].x * ov[j].x + ov[j].y * ov[j].y + ov[j].z * ov[j].z + ov[j].w * ov[j].w;
    }
    wreduce2(s, sq);
    float m = s * (1.f / CD);
    float r = rsqrtf(sq * (1.f / CD) - m * m + 1e-5f);

    float4 xv[3];
    s = 0.f; sq = 0.f;
    #pragma unroll
    for (int j = 0; j < 3; j++) {
        int c = j * 128 + lane * 4;
        float4 g = *(const float4*)(gno + c);
        float4 b = *(const float4*)(bno + c);
        float4 xr = *(const float4*)(x + dst + c);
        xv[j].x = xr.x + (ov[j].x - m) * r * g.x + b.x;
        xv[j].y = xr.y + (ov[j].y - m) * r * g.y + b.y;
        xv[j].z = xr.z + (ov[j].z - m) * r * g.z + b.z;
        xv[j].w = xr.w + (ov[j].w - m) * r * g.w + b.w;
        s += xv[j].x + xv[j].y + xv[j].z + xv[j].w;
        sq += xv[j].x * xv[j].x + xv[j].y * xv[j].y + xv[j].z * xv[j].z + xv[j].w * xv[j].w;
    }
    wreduce2(s, sq);
    float m2 = s * (1.f / CD);
    float r2 = rsqrtf(sq * (1.f / CD) - m2 * m2 + 1e-5f);

    if (lane == 0) sc2[xrow] = make_float2(m2, 1.f / r2);

    #pragma unroll
    for (int j = 0; j < 3; j++) {
        int c = j * 128 + lane * 4;
        *(__half2*)(u2 + dst + c)     = __floats2half2_rn((xv[j].x - m2) * r2, (xv[j].y - m2) * r2);
        *(__half2*)(u2 + dst + c + 2) = __floats2half2_rn((xv[j].z - m2) * r2, (xv[j].w - m2) * r2);
    }
}

// ---------------- host launcher --------------------------------------------
extern "C" void kernel_launch(void* const* d_in, const int* in_sizes, int n_in,
                              void* d_out, int out_size) {
    const float* x   = (const float*)d_in[0];
    const float* g1  = (const float*)d_in[1];
    const float* b1  = (const float*)d_in[2];
    const float* gq  = (const float*)d_in[3];
    const float* bq  = (const float*)d_in[4];
    const float* gk  = (const float*)d_in[5];
    const float* bk  = (const float*)d_in[6];
    const float* gv  = (const float*)d_in[7];
    const float* bv  = (const float*)d_in[8];
    const float* gno = (const float*)d_in[9];
    const float* bno = (const float*)d_in[10];
    const float* ipw = (const float*)d_in[11];
    const float* ipb = (const float*)d_in[12];
    const float* opw = (const float*)d_in[13];
    const float* opb = (const float*)d_in[14];
    const float* g2n = (const float*)d_in[15];
    const float* b2n = (const float*)d_in[16];
    const float* w1  = (const float*)d_in[17];
    const float* b1f = (const float*)d_in[18];
    const float* w2  = (const float*)d_in[19];
    const float* b2f = (const float*)d_in[20];

    int B = in_sizes[0] / (64 * 64 * CD);
    int T = B * 64 * 64;
    int nW = B * 64;

    float *bqkv, *b1p;
    float2 *sc1, *sc2;
    hf *u, *qkv, *obf, *ores, *u2, *hbf, *wqkv, *opwb, *w1b, *w2b;
    cudaGetSymbolAddress((void**)&u,    g_u);
    cudaGetSymbolAddress((void**)&qkv,  g_qkv);
    cudaGetSymbolAddress((void**)&obf,  g_obf);
    cudaGetSymbolAddress((void**)&ores, g_ores);
    cudaGetSymbolAddress((void**)&u2,   g_u2);
    cudaGetSymbolAddress((void**)&hbf,  g_hbf);
    cudaGetSymbolAddress((void**)&sc1,  g_sc1);
    cudaGetSymbolAddress((void**)&sc2,  g_sc2);
    cudaGetSymbolAddress((void**)&wqkv, g_wqkv);
    cudaGetSymbolAddress((void**)&bqkv, g_bqkv);
    cudaGetSymbolAddress((void**)&opwb, g_opw);
    cudaGetSymbolAddress((void**)&w1b,  g_w1);
    cudaGetSymbolAddress((void**)&b1p,  g_b1p);
    cudaGetSymbolAddress((void**)&w2b,  g_w2);

    const int dynsmem = 3 * 2 * SSTG * (int)sizeof(hf);   // 61440
    cudaFuncSetAttribute(k_mma2<0>, cudaFuncAttributeMaxDynamicSharedMemorySize, dynsmem);
    cudaFuncSetAttribute(k_mma2<1>, cudaFuncAttributeMaxDynamicSharedMemorySize, dynsmem);
    cudaFuncSetAttribute(k_mma2<4>, cudaFuncAttributeMaxDynamicSharedMemorySize, dynsmem);
    cudaFuncSetAttribute(k_mma2<5>, cudaFuncAttributeMaxDynamicSharedMemorySize, dynsmem);

    // side stream + events for weight-prep overlap
    static cudaStream_t s2 = nullptr;
    static cudaEvent_t evFork = nullptr, evJoin = nullptr;
    if (!s2) {
        cudaStreamCreateWithFlags(&s2, cudaStreamNonBlocking);
        cudaEventCreateWithFlags(&evFork, cudaEventDisableTiming);
        cudaEventCreateWithFlags(&evJoin, cudaEventDisableTiming);
    }

    cudaEventRecord(evFork, 0);
    cudaStreamWaitEvent(s2, evFork, 0);
    k_wqkv<<<NQKV, 128, 0, s2>>>(ipw, ipb, gq, bq, gk, bk, gv, bv, wqkv, bqkv);
    k_w1p<<<FFD, 128, 0, s2>>>(w1, b1f, g2n, b2n, w1b, b1p);
    k_f2h<<<(CD*CD  + 255) / 256, 256, 0, s2>>>(opw, opwb, CD*CD);
    k_f2h<<<(CD*FFD + 255) / 256, 256, 0, s2>>>(w2,  w2b,  CD*FFD);
    cudaEventRecord(evJoin, s2);

    // 1) LN1 + window partition — overlaps weight prep
    k_prep2<<<T / 8, 256>>>(x, g1, b1, u, sc1);

    cudaStreamWaitEvent(0, evJoin, 0);

    // 2) fused QKV projection
    dim3 thr(256);
    k_mma2<0><<<dim3(NQKV/128, T/128), thr, dynsmem>>>(u, wqkv, bqkv, nullptr, nullptr, qkv, T, NQKV, CD);

    // 3) tensor-core windowed attention
    k_attn2<<<dim3(nW, 12), 128>>>(qkv, obf);

    // 4) out_proj + residual win = u*sig+mu -> ores (fp16)
    k_mma2<4><<<dim3(CD/128, T/128), thr, dynsmem>>>(obf, opwb, opb, u, sc1, ores, T, CD, CD);

    // 5) nout-LN + reverse window + residual + LN2
    k_lnout2<<<T / 8, 256>>>(ores, x, gno, bno, u2, sc2);

    // 6) MLP (fast-tanh GELU in epilogue)
    k_mma2<1><<<dim3(FFD/128, T/128), thr, dynsmem>>>(u2, w1b, b1p, nullptr, nullptr, hbf, T, FFD, CD);
    k_mma2<5><<<dim3(CD/128, T/128), thr, dynsmem>>>(hbf, w2b, b2f, u2, sc2, (float*)d_out, T, CD, FFD);
}